// round 3
// baseline (speedup 1.0000x reference)
#include <cuda_runtime.h>
#include <cuda_bf16.h>
#include <math.h>

// Problem constants (fixed by the reference: B=16, H=W=512)
#define Bn 16
#define Hn 512
#define Wn 512
#define TILE 32
#define FD 34      // feat tile with halo 1 (conv2 needs 3x3 of feat)
#define ID 36      // input tile with halo 2 (feat halo needs 3x3 of input)

// Shared memory layout (floats):
//   s_in  : 3 * 36 * 36      = 3888
//   s_feat: 16 * 34 * 34     = 18496
//   s_w1  : 16*3*3*3         = 432
//   s_b1  : 16
//   s_w2  : 18*16*3*3        = 2592
//   s_b2  : 18
//   s_wk  : 9
// total 25451 floats = 101804 bytes  -> dynamic smem
#define SMEM_FLOATS (3*ID*ID + 16*FD*FD + 432 + 16 + 2592 + 18 + 9)

__global__ __launch_bounds__(256, 2)
void fused_residual_advection(const float* __restrict__ pm25,
                              const float* __restrict__ wind,
                              const float* __restrict__ topo,
                              const float* __restrict__ w1,
                              const float* __restrict__ b1,
                              const float* __restrict__ w2,
                              const float* __restrict__ b2,
                              const float* __restrict__ wk,
                              float* __restrict__ out)
{
    extern __shared__ float smem[];
    float* s_in   = smem;                      // [3][36][36]
    float* s_feat = s_in + 3*ID*ID;            // [16][34][34] (linear idx fy*34+fx)
    float* s_w1   = s_feat + 16*FD*FD;         // [16][27]
    float* s_b1   = s_w1 + 432;
    float* s_w2   = s_b1 + 16;                 // [18][144]
    float* s_b2   = s_w2 + 2592;
    float* s_wk   = s_b2 + 18;

    const int tid = threadIdx.x;
    const int b   = blockIdx.z;
    const int ty0 = blockIdx.y * TILE;
    const int tx0 = blockIdx.x * TILE;

    // ---- load weights/biases into smem ----
    for (int i = tid; i < 432;  i += 256) s_w1[i] = w1[i];
    for (int i = tid; i < 2592; i += 256) s_w2[i] = w2[i];
    if (tid < 16) s_b1[tid] = b1[tid];
    else if (tid >= 32 && tid < 50) s_b2[tid - 32] = b2[tid - 32];
    else if (tid >= 64 && tid < 73) s_wk[tid - 64] = wk[tid - 64];

    // ---- load input halo tile (zero-padded): channels [wind0, wind1, topo] ----
    const int gy0 = ty0 - 2, gx0 = tx0 - 2;
    const float* wind0 = wind + (size_t)b * 2 * Hn * Wn;
    const float* wind1 = wind0 + Hn * Wn;
    const float* topob = topo + (size_t)b * Hn * Wn;
    for (int i = tid; i < ID*ID; i += 256) {
        int ly = i / ID, lx = i - ly * ID;
        int gy = gy0 + ly, gx = gx0 + lx;
        bool ok = (gy >= 0) & (gy < Hn) & (gx >= 0) & (gx < Wn);
        size_t gidx = (size_t)gy * Wn + gx;
        s_in[0*ID*ID + i] = ok ? __ldg(wind0 + gidx) : 0.f;
        s_in[1*ID*ID + i] = ok ? __ldg(wind1 + gidx) : 0.f;
        s_in[2*ID*ID + i] = ok ? __ldg(topob + gidx) : 0.f;
    }
    __syncthreads();

    // ---- phase 2: conv1 + exact GELU -> s_feat (34x34x16), 2 pixels/thread-iter ----
    // Feat pixel idx (fy,fx) corresponds to global (ty0-1+fy, tx0-1+fx).
    // IMPORTANT: feat outside the image is ZERO (conv2's zero padding), not gelu(bias).
    for (int idx = tid; idx < (FD*FD)/2; idx += 256) {
        const int idx2 = idx + (FD*FD)/2;
        const int fyA = idx  / FD, fxA = idx  - fyA * FD;
        const int fyB = idx2 / FD, fxB = idx2 - fyB * FD;
        const bool okA = ((unsigned)(ty0 - 1 + fyA) < Hn) & ((unsigned)(tx0 - 1 + fxA) < Wn);
        const bool okB = ((unsigned)(ty0 - 1 + fyB) < Hn) & ((unsigned)(tx0 - 1 + fxB) < Wn);

        float ra[27], rb[27];
        #pragma unroll
        for (int c = 0; c < 3; c++)
            #pragma unroll
            for (int ky = 0; ky < 3; ky++)
                #pragma unroll
                for (int kx = 0; kx < 3; kx++) {
                    ra[c*9 + ky*3 + kx] = s_in[c*ID*ID + (fyA + ky)*ID + (fxA + kx)];
                    rb[c*9 + ky*3 + kx] = s_in[c*ID*ID + (fyB + ky)*ID + (fxB + kx)];
                }
        #pragma unroll
        for (int o = 0; o < 16; o++) {
            float aA = s_b1[o], aB = aA;
            #pragma unroll
            for (int j = 0; j < 27; j++) {
                float wv = s_w1[o*27 + j];
                aA = fmaf(ra[j], wv, aA);
                aB = fmaf(rb[j], wv, aB);
            }
            // exact GELU: x * Phi(x)
            aA = aA * normcdff(aA);
            aB = aB * normcdff(aB);
            s_feat[o*FD*FD + idx]  = okA ? aA : 0.f;
            s_feat[o*FD*FD + idx2] = okB ? aB : 0.f;
        }
    }
    __syncthreads();

    // ---- phase 3: conv2 (only taps with wk != 0) + bilinear sample + weighted sum ----
    const int lx  = tid & 31;   // output x within tile
    const int ly0 = tid >> 5;   // 0..7; rows ly0 + 8*r, r=0..3
    const float* img = pm25 + (size_t)b * Hn * Wn;

    float acc[4] = {0.f, 0.f, 0.f, 0.f};

    for (int k = 0; k < 9; k++) {
        const float wkv = s_wk[k];
        if (wkv == 0.0f) continue;   // uniform branch; exact (0 * finite = 0)
        const int kdy = k / 3 - 1, kdx = k - (k/3)*3 - 1;

        float dyv[4], dxv[4];
        #pragma unroll
        for (int r = 0; r < 4; r++) { dyv[r] = s_b2[2*k]; dxv[r] = s_b2[2*k + 1]; }

        // conv2 over feat: output channels 2k (dy) and 2k+1 (dx), 4 rows blocked
        #pragma unroll
        for (int c = 0; c < 16; c++) {
            #pragma unroll
            for (int j = 0; j < 9; j++) {
                const int ky = j / 3, kx = j - ky*3;
                const float wdy = s_w2[(2*k)    *144 + c*9 + j];
                const float wdx = s_w2[(2*k + 1)*144 + c*9 + j];
                #pragma unroll
                for (int r = 0; r < 4; r++) {
                    // output pixel (ly0+8r, lx) -> feat window starts at feat idx (ly0+8r, lx)
                    float f = s_feat[c*FD*FD + (ly0 + 8*r + ky)*FD + (lx + kx)];
                    dyv[r] = fmaf(f, wdy, dyv[r]);
                    dxv[r] = fmaf(f, wdx, dxv[r]);
                }
            }
        }

        #pragma unroll
        for (int r = 0; r < 4; r++) {
            const int gy = ty0 + ly0 + 8*r;
            const int gx = tx0 + lx;
            const float py = (float)(gy + kdy) + dyv[r];
            const float px = (float)(gx + kdx) + dxv[r];
            const float y0f = floorf(py), x0f = floorf(px);
            const float wy = py - y0f, wx = px - x0f;
            const int y0 = (int)y0f, x0 = (int)x0f;
            const int y1 = y0 + 1,  x1 = x0 + 1;
            const bool okY0 = (y0 >= 0) & (y0 < Hn);
            const bool okY1 = (y1 >= 0) & (y1 < Hn);
            const bool okX0 = (x0 >= 0) & (x0 < Wn);
            const bool okX1 = (x1 >= 0) & (x1 < Wn);
            const float v00 = (okY0 & okX0) ? __ldg(img + (size_t)y0*Wn + x0) : 0.f;
            const float v01 = (okY0 & okX1) ? __ldg(img + (size_t)y0*Wn + x1) : 0.f;
            const float v10 = (okY1 & okX0) ? __ldg(img + (size_t)y1*Wn + x0) : 0.f;
            const float v11 = (okY1 & okX1) ? __ldg(img + (size_t)y1*Wn + x1) : 0.f;
            const float s = v00*(1.f - wy)*(1.f - wx) + v01*(1.f - wy)*wx
                          + v10*wy*(1.f - wx)         + v11*wy*wx;
            acc[r] = fmaf(wkv, s, acc[r]);
        }
    }

    #pragma unroll
    for (int r = 0; r < 4; r++) {
        const int gy = ty0 + ly0 + 8*r;
        out[(size_t)b * Hn * Wn + (size_t)gy * Wn + (tx0 + lx)] = acc[r];
    }
}

extern "C" void kernel_launch(void* const* d_in, const int* in_sizes, int n_in,
                              void* d_out, int out_size)
{
    // metadata order: pm25, avg_wind, topo, conv1_w, conv1_b, conv2_w, conv2_b, weight
    const float* pm25 = (const float*)d_in[0];
    const float* wind = (const float*)d_in[1];
    const float* topo = (const float*)d_in[2];
    const float* w1   = (const float*)d_in[3];
    const float* b1   = (const float*)d_in[4];
    const float* w2   = (const float*)d_in[5];
    const float* b2   = (const float*)d_in[6];
    const float* wk   = (const float*)d_in[7];
    float* out = (float*)d_out;

    const size_t smem_bytes = (size_t)SMEM_FLOATS * sizeof(float);
    // Idempotent; first (non-captured) correctness call sets it, later calls no-op.
    cudaFuncSetAttribute(fused_residual_advection,
                         cudaFuncAttributeMaxDynamicSharedMemorySize,
                         (int)smem_bytes);

    dim3 grid(Wn / TILE, Hn / TILE, Bn);
    fused_residual_advection<<<grid, 256, smem_bytes>>>(
        pm25, wind, topo, w1, b1, w2, b2, wk, out);
}

// round 4
// speedup vs baseline: 1.0118x; 1.0118x over previous
#include <cuda_runtime.h>
#include <cuda_bf16.h>
#include <math.h>

// Fixed problem shape: B=16, H=W=512
#define Bn 16
#define Hn 512
#define Wn 512
#define TILE 32
#define FD  34      // feat tile rows (halo 1)
#define FDP 36      // feat row pitch (padded for aligned float4 x-loads)
#define ID  36      // input tile with halo 2

// smem floats:
//  s_in   3*36*36            = 3888
//  s_feat 16*34*36           = 19584
//  s_w1t  27*16              = 432   ([j][o])
//  s_b1   16
//  s_w2t  18*9*16            = 2592  ([och][j][c])
//  s_b2   18
//  s_wk   9
#define SMEM_FLOATS (3*ID*ID + 16*FD*FDP + 432 + 16 + 2592 + 18 + 9)

__global__ __launch_bounds__(256, 2)
void fused_residual_advection(const float* __restrict__ pm25,
                              const float* __restrict__ wind,
                              const float* __restrict__ topo,
                              const float* __restrict__ w1,
                              const float* __restrict__ b1,
                              const float* __restrict__ w2,
                              const float* __restrict__ b2,
                              const float* __restrict__ wk,
                              float* __restrict__ out)
{
    extern __shared__ float smem[];
    float* s_in   = smem;                       // [3][36][36]
    float* s_feat = s_in + 3*ID*ID;             // [16][34][36]
    float* s_w1t  = s_feat + 16*FD*FDP;         // [27][16]
    float* s_b1   = s_w1t + 432;
    float* s_w2t  = s_b1 + 16;                  // [18][9][16]
    float* s_b2   = s_w2t + 2592;
    float* s_wk   = s_b2 + 18;

    const int tid = threadIdx.x;
    const int b   = blockIdx.z;
    const int ty0 = blockIdx.y * TILE;
    const int tx0 = blockIdx.x * TILE;

    // ---- load + transpose weights into smem ----
    for (int i = tid; i < 432; i += 256) {
        int o = i / 27, j = i - o * 27;
        s_w1t[j*16 + o] = w1[i];
    }
    for (int i = tid; i < 2592; i += 256) {
        int och = i / 144, r = i - och * 144;
        int c = r / 9, j = r - c * 9;
        s_w2t[och*144 + j*16 + c] = w2[i];
    }
    if (tid < 16) s_b1[tid] = b1[tid];
    else if (tid >= 32 && tid < 50) s_b2[tid - 32] = b2[tid - 32];
    else if (tid >= 64 && tid < 73) s_wk[tid - 64] = wk[tid - 64];

    // ---- load zero-padded input halo: [wind0, wind1, topo] ----
    const int gy0 = ty0 - 2, gx0 = tx0 - 2;
    const float* wind0 = wind + (size_t)b * 2 * Hn * Wn;
    const float* wind1 = wind0 + Hn * Wn;
    const float* topob = topo + (size_t)b * Hn * Wn;
    for (int i = tid; i < ID*ID; i += 256) {
        int ly = i / ID, lx = i - ly * ID;
        int gy = gy0 + ly, gx = gx0 + lx;
        bool ok = (gy >= 0) & (gy < Hn) & (gx >= 0) & (gx < Wn);
        size_t gidx = (size_t)gy * Wn + gx;
        s_in[0*ID*ID + i] = ok ? __ldg(wind0 + gidx) : 0.f;
        s_in[1*ID*ID + i] = ok ? __ldg(wind1 + gidx) : 0.f;
        s_in[2*ID*ID + i] = ok ? __ldg(topob + gidx) : 0.f;
    }
    __syncthreads();

    // ---- phase 2: conv1 + exact GELU -> s_feat, j-outer, vector weights ----
    // feat (fy,fx) <-> global (ty0-1+fy, tx0-1+fx); out-of-image feat = 0
    // (that is conv2's zero padding).
    for (int idx = tid; idx < (FD*FD)/2; idx += 256) {
        const int idx2 = idx + (FD*FD)/2;
        const int fyA = idx  / FD, fxA = idx  - fyA * FD;
        const int fyB = idx2 / FD, fxB = idx2 - fyB * FD;
        const bool okA = ((unsigned)(ty0 - 1 + fyA) < Hn) & ((unsigned)(tx0 - 1 + fxA) < Wn);
        const bool okB = ((unsigned)(ty0 - 1 + fyB) < Hn) & ((unsigned)(tx0 - 1 + fxB) < Wn);

        float aA[16], aB[16];
        #pragma unroll
        for (int o = 0; o < 16; o++) { aA[o] = s_b1[o]; aB[o] = aA[o]; }

        #pragma unroll
        for (int j = 0; j < 27; j++) {
            const int c  = j / 9;
            const int ky = (j - c * 9) / 3;
            const int kx = j - c * 9 - ky * 3;
            const float vA = s_in[c*ID*ID + (fyA + ky)*ID + (fxA + kx)];
            const float vB = s_in[c*ID*ID + (fyB + ky)*ID + (fxB + kx)];
            const float4 w0 = *(const float4*)&s_w1t[j*16 + 0];
            const float4 w1v= *(const float4*)&s_w1t[j*16 + 4];
            const float4 w2v= *(const float4*)&s_w1t[j*16 + 8];
            const float4 w3 = *(const float4*)&s_w1t[j*16 + 12];
            const float wv[16] = {w0.x,w0.y,w0.z,w0.w, w1v.x,w1v.y,w1v.z,w1v.w,
                                  w2v.x,w2v.y,w2v.z,w2v.w, w3.x,w3.y,w3.z,w3.w};
            #pragma unroll
            for (int o = 0; o < 16; o++) {
                aA[o] = fmaf(vA, wv[o], aA[o]);
                aB[o] = fmaf(vB, wv[o], aB[o]);
            }
        }
        #pragma unroll
        for (int o = 0; o < 16; o++) {
            float gA = aA[o] * normcdff(aA[o]);   // exact GELU
            float gB = aB[o] * normcdff(aB[o]);
            s_feat[o*FD*FDP + fyA*FDP + fxA] = okA ? gA : 0.f;
            s_feat[o*FD*FDP + fyB*FDP + fxB] = okB ? gB : 0.f;
        }
    }
    __syncthreads();

    // ---- phase 3: conv2 (active taps only) + bilinear + weighted sum ----
    // thread -> 4 consecutive x outputs: row = tid/8, x0 = 4*(tid%8)
    const int x0  = (tid & 7) * 4;
    const int row = tid >> 3;
    const float* img = pm25 + (size_t)b * Hn * Wn;

    float acc[4] = {0.f, 0.f, 0.f, 0.f};

    for (int k = 0; k < 9; k++) {
        const float wkv = s_wk[k];
        if (wkv == 0.0f) continue;          // uniform branch, value-exact
        const int kdy = k / 3 - 1, kdx = k - (k/3)*3 - 1;

        float dyv[4], dxv[4];
        #pragma unroll
        for (int i = 0; i < 4; i++) { dyv[i] = s_b2[2*k]; dxv[i] = s_b2[2*k + 1]; }

        #pragma unroll
        for (int c = 0; c < 16; c++) {
            // 3 feat rows x 8 floats, two aligned float4 loads each
            float f[3][8];
            const float* base = &s_feat[c*FD*FDP + row*FDP + x0];
            #pragma unroll
            for (int ky = 0; ky < 3; ky++) {
                const float4 p0 = *(const float4*)(base + ky*FDP);
                const float4 p1 = *(const float4*)(base + ky*FDP + 4);
                f[ky][0]=p0.x; f[ky][1]=p0.y; f[ky][2]=p0.z; f[ky][3]=p0.w;
                f[ky][4]=p1.x; f[ky][5]=p1.y; f[ky][6]=p1.z; f[ky][7]=p1.w;
            }
            #pragma unroll
            for (int j = 0; j < 9; j++) {
                const int ky = j / 3, kx = j - ky*3;
                const float wdy = s_w2t[(2*k)    *144 + j*16 + c];
                const float wdx = s_w2t[(2*k + 1)*144 + j*16 + c];
                #pragma unroll
                for (int i = 0; i < 4; i++) {
                    dyv[i] = fmaf(f[ky][kx + i], wdy, dyv[i]);
                    dxv[i] = fmaf(f[ky][kx + i], wdx, dxv[i]);
                }
            }
        }

        #pragma unroll
        for (int i = 0; i < 4; i++) {
            const int gy = ty0 + row;
            const int gx = tx0 + x0 + i;
            const float py = (float)(gy + kdy) + dyv[i];
            const float px = (float)(gx + kdx) + dxv[i];
            const float y0f = floorf(py), x0f = floorf(px);
            const float wy = py - y0f, wx = px - x0f;
            const int yy0 = (int)y0f, xx0 = (int)x0f;
            const int yy1 = yy0 + 1,  xx1 = xx0 + 1;
            const bool okY0 = (yy0 >= 0) & (yy0 < Hn);
            const bool okY1 = (yy1 >= 0) & (yy1 < Hn);
            const bool okX0 = (xx0 >= 0) & (xx0 < Wn);
            const bool okX1 = (xx1 >= 0) & (xx1 < Wn);
            const float v00 = (okY0 & okX0) ? __ldg(img + (size_t)yy0*Wn + xx0) : 0.f;
            const float v01 = (okY0 & okX1) ? __ldg(img + (size_t)yy0*Wn + xx1) : 0.f;
            const float v10 = (okY1 & okX0) ? __ldg(img + (size_t)yy1*Wn + xx0) : 0.f;
            const float v11 = (okY1 & okX1) ? __ldg(img + (size_t)yy1*Wn + xx1) : 0.f;
            const float s = v00*(1.f - wy)*(1.f - wx) + v01*(1.f - wy)*wx
                          + v10*wy*(1.f - wx)         + v11*wy*wx;
            acc[i] = fmaf(wkv, s, acc[i]);
        }
    }

    // aligned float4 store
    float4 o4; o4.x = acc[0]; o4.y = acc[1]; o4.z = acc[2]; o4.w = acc[3];
    *(float4*)&out[(size_t)b * Hn * Wn + (size_t)(ty0 + row) * Wn + (tx0 + x0)] = o4;
}

extern "C" void kernel_launch(void* const* d_in, const int* in_sizes, int n_in,
                              void* d_out, int out_size)
{
    const float* pm25 = (const float*)d_in[0];
    const float* wind = (const float*)d_in[1];
    const float* topo = (const float*)d_in[2];
    const float* w1   = (const float*)d_in[3];
    const float* b1   = (const float*)d_in[4];
    const float* w2   = (const float*)d_in[5];
    const float* b2   = (const float*)d_in[6];
    const float* wk   = (const float*)d_in[7];
    float* out = (float*)d_out;

    const size_t smem_bytes = (size_t)SMEM_FLOATS * sizeof(float);
    cudaFuncSetAttribute(fused_residual_advection,
                         cudaFuncAttributeMaxDynamicSharedMemorySize,
                         (int)smem_bytes);

    dim3 grid(Wn / TILE, Hn / TILE, Bn);
    fused_residual_advection<<<grid, 256, smem_bytes>>>(
        pm25, wind, topo, w1, b1, w2, b2, wk, out);
}

// round 5
// speedup vs baseline: 1.3859x; 1.3697x over previous
#include <cuda_runtime.h>
#include <cuda_bf16.h>
#include <math.h>

// Fixed problem shape: B=16, H=W=512
#define Bn 16
#define Hn 512
#define Wn 512
#define TILE 32
#define FD  34      // feat tile rows/cols (halo 1)
#define FDP 36      // feat row pitch (float4-aligned x loads)
#define ID  36      // input tile with halo 2

// smem floats:
//  s_in   3*36*36 = 3888   (reused as dup-weight table, 576 floats, in phase 3)
//  s_feat 16*34*36 = 19584
//  s_w1t  27*16   = 432    ([j][o])
//  s_b1   16
//  s_b2   18
//  s_wk   9
#define SMEM_FLOATS (3*ID*ID + 16*FD*FDP + 432 + 16 + 18 + 9)

typedef unsigned long long ull;

__device__ __forceinline__ ull pack2(float lo, float hi) {
    ull r; asm("mov.b64 %0, {%1, %2};" : "=l"(r) : "f"(lo), "f"(hi)); return r;
}
__device__ __forceinline__ void unpack2(ull v, float& lo, float& hi) {
    asm("mov.b64 {%0, %1}, %2;" : "=f"(lo), "=f"(hi) : "l"(v));
}
// d = a*b + d, two fp32 lanes per instruction (exact fp32 FMA per lane)
__device__ __forceinline__ void ffma2(ull& d, ull a, ull b) {
    asm("fma.rn.f32x2 %0, %1, %2, %0;" : "+l"(d) : "l"(a), "l"(b));
}

__device__ __forceinline__ float gelu_exact(float x) {
    return 0.5f * x * (1.0f + erff(x * 0.70710678118654752440f));
}

__global__ __launch_bounds__(256, 2)
void fused_residual_advection(const float* __restrict__ pm25,
                              const float* __restrict__ wind,
                              const float* __restrict__ topo,
                              const float* __restrict__ w1,
                              const float* __restrict__ b1,
                              const float* __restrict__ w2,
                              const float* __restrict__ b2,
                              const float* __restrict__ wk,
                              float* __restrict__ out)
{
    extern __shared__ float smem[];
    float* s_in   = smem;                       // [3][36][36]; phase 3: dup-w table
    float* s_feat = s_in + 3*ID*ID;             // [16][34][36] planar
    float* s_w1t  = s_feat + 16*FD*FDP;         // [27][16]
    float* s_b1   = s_w1t + 432;
    float* s_b2   = s_b1 + 16;
    float* s_wk   = s_b2 + 18;

    const int tid = threadIdx.x;
    const int b   = blockIdx.z;
    const int ty0 = blockIdx.y * TILE;
    const int tx0 = blockIdx.x * TILE;

    // ---- weights/bias to smem (w1 transposed to [j][o]) ----
    for (int i = tid; i < 432; i += 256) {
        int o = i / 27, j = i - o * 27;
        s_w1t[j*16 + o] = w1[i];
    }
    if (tid < 16) s_b1[tid] = b1[tid];
    else if (tid >= 32 && tid < 50) s_b2[tid - 32] = b2[tid - 32];
    else if (tid >= 64 && tid < 73) s_wk[tid - 64] = wk[tid - 64];

    // ---- zero-padded input halo: [wind0, wind1, topo] ----
    const int gy0 = ty0 - 2, gx0 = tx0 - 2;
    const float* wind0 = wind + (size_t)b * 2 * Hn * Wn;
    const float* wind1 = wind0 + Hn * Wn;
    const float* topob = topo + (size_t)b * Hn * Wn;
    for (int i = tid; i < ID*ID; i += 256) {
        int ly = i / ID, lx = i - ly * ID;
        int gy = gy0 + ly, gx = gx0 + lx;
        bool ok = (gy >= 0) & (gy < Hn) & (gx >= 0) & (gx < Wn);
        size_t gidx = (size_t)gy * Wn + gx;
        s_in[0*ID*ID + i] = ok ? __ldg(wind0 + gidx) : 0.f;
        s_in[1*ID*ID + i] = ok ? __ldg(wind1 + gidx) : 0.f;
        s_in[2*ID*ID + i] = ok ? __ldg(topob + gidx) : 0.f;
    }
    __syncthreads();

    // ---- phase 2: conv1 + GELU -> s_feat; f32x2 over channel pairs ----
    // feat (fy,fx) <-> global (ty0-1+fy, tx0-1+fx); out-of-image feat = 0.
    {
        ull b1p[8];
        #pragma unroll
        for (int p = 0; p < 8; p++) b1p[p] = pack2(s_b1[2*p], s_b1[2*p + 1]);

        const int half = (FD*FD)/2;   // 578
        for (int idx = tid; idx < half; idx += 256) {
            const int idx2 = idx + half;
            const int fyA = idx  / FD, fxA = idx  - fyA * FD;
            const int fyB = idx2 / FD, fxB = idx2 - fyB * FD;
            const bool okA = ((unsigned)(ty0 - 1 + fyA) < Hn) & ((unsigned)(tx0 - 1 + fxA) < Wn);
            const bool okB = ((unsigned)(ty0 - 1 + fyB) < Hn) & ((unsigned)(tx0 - 1 + fxB) < Wn);
            const int baseA = fyA*ID + fxA, baseB = fyB*ID + fxB;

            ull aA[8], aB[8];
            #pragma unroll
            for (int p = 0; p < 8; p++) { aA[p] = b1p[p]; aB[p] = b1p[p]; }

            #pragma unroll
            for (int j = 0; j < 27; j++) {
                const int c  = j / 9;
                const int r9 = j - c * 9;
                const int ky = r9 / 3, kx = r9 - ky * 3;
                const float vA = s_in[c*ID*ID + baseA + ky*ID + kx];
                const float vB = s_in[c*ID*ID + baseB + ky*ID + kx];
                const ull vA2 = pack2(vA, vA);
                const ull vB2 = pack2(vB, vB);
                const ulonglong2* wp = (const ulonglong2*)&s_w1t[j*16];
                const ulonglong2 w01 = wp[0], w23 = wp[1], w45 = wp[2], w67 = wp[3];
                ffma2(aA[0], vA2, w01.x); ffma2(aA[1], vA2, w01.y);
                ffma2(aA[2], vA2, w23.x); ffma2(aA[3], vA2, w23.y);
                ffma2(aA[4], vA2, w45.x); ffma2(aA[5], vA2, w45.y);
                ffma2(aA[6], vA2, w67.x); ffma2(aA[7], vA2, w67.y);
                ffma2(aB[0], vB2, w01.x); ffma2(aB[1], vB2, w01.y);
                ffma2(aB[2], vB2, w23.x); ffma2(aB[3], vB2, w23.y);
                ffma2(aB[4], vB2, w45.x); ffma2(aB[5], vB2, w45.y);
                ffma2(aB[6], vB2, w67.x); ffma2(aB[7], vB2, w67.y);
            }

            #pragma unroll
            for (int p = 0; p < 8; p++) {
                float g0, g1;
                unpack2(aA[p], g0, g1);
                g0 = gelu_exact(g0); g1 = gelu_exact(g1);
                s_feat[(2*p)  *FD*FDP + fyA*FDP + fxA] = okA ? g0 : 0.f;
                s_feat[(2*p+1)*FD*FDP + fyA*FDP + fxA] = okA ? g1 : 0.f;
                unpack2(aB[p], g0, g1);
                g0 = gelu_exact(g0); g1 = gelu_exact(g1);
                s_feat[(2*p)  *FD*FDP + fyB*FDP + fxB] = okB ? g0 : 0.f;
                s_feat[(2*p+1)*FD*FDP + fyB*FDP + fxB] = okB ? g1 : 0.f;
            }
        }
    }
    __syncthreads();

    // ---- phase 3: conv2 (active taps) + bilinear, f32x2 over x-pairs ----
    const int x0  = (tid & 7) * 4;
    const int row = tid >> 3;
    const float* img = pm25 + (size_t)b * Hn * Wn;
    float* s_wdup = s_in;    // s_in is dead now; 576-float dup-weight table

    float acc[4] = {0.f, 0.f, 0.f, 0.f};

    for (int k = 0; k < 9; k++) {
        const float wkv = s_wk[k];
        if (wkv == 0.0f) continue;          // uniform across grid, value-exact
        const int kdy = k / 3 - 1, kdx = k - (k/3)*3 - 1;

        // build duplicated-weight table for this tap's two channels (2k, 2k+1)
        __syncthreads();
        for (int i = tid; i < 288; i += 256) {
            const int d  = i / 144;
            const int r  = i - d * 144;
            const int c  = r / 9;
            const int j  = r - c * 9;
            const float w = __ldg(&w2[(size_t)(2*k + d)*144 + c*9 + j]);
            s_wdup[d*288 + j*32 + c*2 + 0] = w;
            s_wdup[d*288 + j*32 + c*2 + 1] = w;
        }
        __syncthreads();

        const float bdy = s_b2[2*k], bdx = s_b2[2*k + 1];
        ull ady0 = pack2(bdy, bdy), ady1 = ady0;
        ull adx0 = pack2(bdx, bdx), adx1 = adx0;

        #pragma unroll
        for (int c = 0; c < 16; c++) {
            const float* fb = s_feat + c*FD*FDP + row*FDP + x0;
            ull P[3][5];
            #pragma unroll
            for (int ky = 0; ky < 3; ky++) {
                const float* rp = fb + ky*FDP;
                const ulonglong2 q0 = *(const ulonglong2*)rp;   // {f0,f1},{f2,f3}
                const ull        q1 = *(const ull*)(rp + 4);    // {f4,f5}
                float f0, f1, f2, f3, f4, f5;
                unpack2(q0.x, f0, f1);
                unpack2(q0.y, f2, f3);
                unpack2(q1,   f4, f5);
                P[ky][0] = q0.x;
                P[ky][2] = q0.y;
                P[ky][4] = q1;
                P[ky][1] = pack2(f1, f2);
                P[ky][3] = pack2(f3, f4);
            }
            #pragma unroll
            for (int ky = 0; ky < 3; ky++) {
                #pragma unroll
                for (int kx = 0; kx < 3; kx++) {
                    const int jj = ky*3 + kx;
                    const ull wy2 = *(const ull*)&s_wdup[jj*32 + c*2];
                    const ull wx2 = *(const ull*)&s_wdup[288 + jj*32 + c*2];
                    ffma2(ady0, P[ky][kx],     wy2);
                    ffma2(ady1, P[ky][kx + 2], wy2);
                    ffma2(adx0, P[ky][kx],     wx2);
                    ffma2(adx1, P[ky][kx + 2], wx2);
                }
            }
        }

        float dyv[4], dxv[4];
        unpack2(ady0, dyv[0], dyv[1]); unpack2(ady1, dyv[2], dyv[3]);
        unpack2(adx0, dxv[0], dxv[1]); unpack2(adx1, dxv[2], dxv[3]);

        #pragma unroll
        for (int i = 0; i < 4; i++) {
            const int gy = ty0 + row;
            const int gx = tx0 + x0 + i;
            const float py = (float)(gy + kdy) + dyv[i];
            const float px = (float)(gx + kdx) + dxv[i];
            const float y0f = floorf(py), x0f = floorf(px);
            const float wy = py - y0f, wx = px - x0f;
            const int yy0 = (int)y0f, xx0 = (int)x0f;
            const int yy1 = yy0 + 1,  xx1 = xx0 + 1;
            const bool okY0 = (yy0 >= 0) & (yy0 < Hn);
            const bool okY1 = (yy1 >= 0) & (yy1 < Hn);
            const bool okX0 = (xx0 >= 0) & (xx0 < Wn);
            const bool okX1 = (xx1 >= 0) & (xx1 < Wn);
            const float v00 = (okY0 & okX0) ? __ldg(img + (size_t)yy0*Wn + xx0) : 0.f;
            const float v01 = (okY0 & okX1) ? __ldg(img + (size_t)yy0*Wn + xx1) : 0.f;
            const float v10 = (okY1 & okX0) ? __ldg(img + (size_t)yy1*Wn + xx0) : 0.f;
            const float v11 = (okY1 & okX1) ? __ldg(img + (size_t)yy1*Wn + xx1) : 0.f;
            const float s = v00*(1.f - wy)*(1.f - wx) + v01*(1.f - wy)*wx
                          + v10*wy*(1.f - wx)         + v11*wy*wx;
            acc[i] = fmaf(wkv, s, acc[i]);
        }
    }

    float4 o4; o4.x = acc[0]; o4.y = acc[1]; o4.z = acc[2]; o4.w = acc[3];
    *(float4*)&out[(size_t)b * Hn * Wn + (size_t)(ty0 + row) * Wn + (tx0 + x0)] = o4;
}

extern "C" void kernel_launch(void* const* d_in, const int* in_sizes, int n_in,
                              void* d_out, int out_size)
{
    const float* pm25 = (const float*)d_in[0];
    const float* wind = (const float*)d_in[1];
    const float* topo = (const float*)d_in[2];
    const float* w1   = (const float*)d_in[3];
    const float* b1   = (const float*)d_in[4];
    const float* w2   = (const float*)d_in[5];
    const float* b2   = (const float*)d_in[6];
    const float* wk   = (const float*)d_in[7];
    float* out = (float*)d_out;

    const size_t smem_bytes = (size_t)SMEM_FLOATS * sizeof(float);
    cudaFuncSetAttribute(fused_residual_advection,
                         cudaFuncAttributeMaxDynamicSharedMemorySize,
                         (int)smem_bytes);

    dim3 grid(Wn / TILE, Hn / TILE, Bn);
    fused_residual_advection<<<grid, 256, smem_bytes>>>(
        pm25, wind, topo, w1, b1, w2, b2, wk, out);
}

// round 6
// speedup vs baseline: 1.5205x; 1.0971x over previous
#include <cuda_runtime.h>
#include <cuda_bf16.h>
#include <math.h>

// Fixed problem shape: B=16, H=W=512
#define Bn 16
#define Hn 512
#define Wn 512
#define TILE 32
#define FD  34
#define FDP 36
#define ID  36

#define SMEM_FLOATS (3*ID*ID + 16*FD*FDP + 432 + 16 + 18 + 9)

typedef unsigned long long ull;

__device__ __forceinline__ ull pack2(float lo, float hi) {
    ull r; asm("mov.b64 %0, {%1, %2};" : "=l"(r) : "f"(lo), "f"(hi)); return r;
}
__device__ __forceinline__ void unpack2(ull v, float& lo, float& hi) {
    asm("mov.b64 {%0, %1}, %2;" : "=f"(lo), "=f"(hi) : "l"(v));
}
__device__ __forceinline__ void ffma2(ull& d, ull a, ull b) {
    asm("fma.rn.f32x2 %0, %1, %2, %0;" : "+l"(d) : "l"(a), "l"(b));
}
__device__ __forceinline__ ull fma2v(ull a, ull b, ull c) {
    ull r; asm("fma.rn.f32x2 %0, %1, %2, %3;" : "=l"(r) : "l"(a), "l"(b), "l"(c)); return r;
}
__device__ __forceinline__ ull mul2(ull a, ull b) {
    ull r; asm("mul.rn.f32x2 %0, %1, %2;" : "=l"(r) : "l"(a), "l"(b)); return r;
}
__device__ __forceinline__ ull add2(ull a, ull b) {
    ull r; asm("add.rn.f32x2 %0, %1, %2;" : "=l"(r) : "l"(a), "l"(b)); return r;
}

// Exact-GELU for 2 packed fp32 lanes.
// Phi via Abramowitz-Stegun 26.2.17 (|err| < 7.5e-8), coeffs pre-scaled by 1/sqrt(2pi).
// Phi(x) = 0.5 + sign(x) * (0.5 - exp(-x^2/2)*poly(t)),  t = 1/(1 + 0.2316419|x|)
__device__ __forceinline__ ull gelu2(ull x2) {
    ull a2;  asm("and.b64 %0, %1, %2;" : "=l"(a2) : "l"(x2), "l"(0x7FFFFFFF7FFFFFFFULL));
    ull d2 = fma2v(pack2(0.2316419f, 0.2316419f), a2, pack2(1.0f, 1.0f));
    float dlo, dhi; unpack2(d2, dlo, dhi);
    float tlo, thi;
    asm("rcp.approx.f32 %0, %1;" : "=f"(tlo) : "f"(dlo));
    asm("rcp.approx.f32 %0, %1;" : "=f"(thi) : "f"(dhi));
    ull t2 = pack2(tlo, thi);
    ull m2 = mul2(a2, a2);
    ull g2 = mul2(m2, pack2(-0.72134752f, -0.72134752f));  // -x^2 * log2(e)/2
    float glo, ghi; unpack2(g2, glo, ghi);
    float elo, ehi;
    asm("ex2.approx.f32 %0, %1;" : "=f"(elo) : "f"(glo));
    asm("ex2.approx.f32 %0, %1;" : "=f"(ehi) : "f"(ghi));
    ull e2 = pack2(elo, ehi);
    ull u = fma2v(pack2( 0.53070279f,  0.53070279f), t2, pack2(-0.72657601f, -0.72657601f));
    u = fma2v(u, t2, pack2( 0.71070696f,  0.71070696f));
    u = fma2v(u, t2, pack2(-0.14224837f, -0.14224837f));
    u = fma2v(u, t2, pack2( 0.12741480f,  0.12741480f));
    u = mul2(u, t2);
    ull q2 = mul2(e2, u);                                           // upper-tail, in [0, 0.5]
    ull h2 = fma2v(q2, pack2(-1.0f, -1.0f), pack2(0.5f, 0.5f));     // 0.5 - q  (>= 0)
    ull s2;  asm("and.b64 %0, %1, %2;" : "=l"(s2) : "l"(x2), "l"(0x8000000080000000ULL));
    ull sh2; asm("or.b64  %0, %1, %2;" : "=l"(sh2) : "l"(s2), "l"(h2));  // sign(x)*(0.5-q)
    ull phi2 = add2(sh2, pack2(0.5f, 0.5f));
    return mul2(x2, phi2);
}

__global__ __launch_bounds__(256, 2)
void fused_residual_advection(const float* __restrict__ pm25,
                              const float* __restrict__ wind,
                              const float* __restrict__ topo,
                              const float* __restrict__ w1,
                              const float* __restrict__ b1,
                              const float* __restrict__ w2,
                              const float* __restrict__ b2,
                              const float* __restrict__ wk,
                              float* __restrict__ out)
{
    extern __shared__ float smem[];
    float* s_in   = smem;                       // [3][36][36]; phase 3: dup-weight table
    float* s_feat = s_in + 3*ID*ID;             // [16][34][36] planar
    float* s_w1t  = s_feat + 16*FD*FDP;         // [27][16]
    float* s_b1   = s_w1t + 432;
    float* s_b2   = s_b1 + 16;
    float* s_wk   = s_b2 + 18;

    const int tid = threadIdx.x;
    const int b   = blockIdx.z;
    const int ty0 = blockIdx.y * TILE;
    const int tx0 = blockIdx.x * TILE;

    for (int i = tid; i < 432; i += 256) {
        int o = i / 27, j = i - o * 27;
        s_w1t[j*16 + o] = w1[i];
    }
    if (tid < 16) s_b1[tid] = b1[tid];
    else if (tid >= 32 && tid < 50) s_b2[tid - 32] = b2[tid - 32];
    else if (tid >= 64 && tid < 73) s_wk[tid - 64] = wk[tid - 64];

    const int gy0 = ty0 - 2, gx0 = tx0 - 2;
    const float* wind0 = wind + (size_t)b * 2 * Hn * Wn;
    const float* wind1 = wind0 + Hn * Wn;
    const float* topob = topo + (size_t)b * Hn * Wn;
    for (int i = tid; i < ID*ID; i += 256) {
        int ly = i / ID, lx = i - ly * ID;
        int gy = gy0 + ly, gx = gx0 + lx;
        bool ok = (gy >= 0) & (gy < Hn) & (gx >= 0) & (gx < Wn);
        size_t gidx = (size_t)gy * Wn + gx;
        s_in[0*ID*ID + i] = ok ? __ldg(wind0 + gidx) : 0.f;
        s_in[1*ID*ID + i] = ok ? __ldg(wind1 + gidx) : 0.f;
        s_in[2*ID*ID + i] = ok ? __ldg(topob + gidx) : 0.f;
    }
    __syncthreads();

    // ---- phase 2: conv1 + GELU -> s_feat; f32x2 channel pairs ----
    {
        ull b1p[8];
        #pragma unroll
        for (int p = 0; p < 8; p++) b1p[p] = pack2(s_b1[2*p], s_b1[2*p + 1]);

        const int half = (FD*FD)/2;   // 578
        for (int idx = tid; idx < half; idx += 256) {
            const int idx2 = idx + half;
            const int fyA = idx  / FD, fxA = idx  - fyA * FD;
            const int fyB = idx2 / FD, fxB = idx2 - fyB * FD;
            const bool okA = ((unsigned)(ty0 - 1 + fyA) < Hn) & ((unsigned)(tx0 - 1 + fxA) < Wn);
            const bool okB = ((unsigned)(ty0 - 1 + fyB) < Hn) & ((unsigned)(tx0 - 1 + fxB) < Wn);
            const int baseA = fyA*ID + fxA, baseB = fyB*ID + fxB;

            ull aA[8], aB[8];
            #pragma unroll
            for (int p = 0; p < 8; p++) { aA[p] = b1p[p]; aB[p] = b1p[p]; }

            #pragma unroll
            for (int j = 0; j < 27; j++) {
                const int c  = j / 9;
                const int r9 = j - c * 9;
                const int ky = r9 / 3, kx = r9 - ky * 3;
                const float vA = s_in[c*ID*ID + baseA + ky*ID + kx];
                const float vB = s_in[c*ID*ID + baseB + ky*ID + kx];
                const ull vA2 = pack2(vA, vA);
                const ull vB2 = pack2(vB, vB);
                const ulonglong2* wp = (const ulonglong2*)&s_w1t[j*16];
                const ulonglong2 w01 = wp[0], w23 = wp[1], w45 = wp[2], w67 = wp[3];
                ffma2(aA[0], vA2, w01.x); ffma2(aA[1], vA2, w01.y);
                ffma2(aA[2], vA2, w23.x); ffma2(aA[3], vA2, w23.y);
                ffma2(aA[4], vA2, w45.x); ffma2(aA[5], vA2, w45.y);
                ffma2(aA[6], vA2, w67.x); ffma2(aA[7], vA2, w67.y);
                ffma2(aB[0], vB2, w01.x); ffma2(aB[1], vB2, w01.y);
                ffma2(aB[2], vB2, w23.x); ffma2(aB[3], vB2, w23.y);
                ffma2(aB[4], vB2, w45.x); ffma2(aB[5], vB2, w45.y);
                ffma2(aB[6], vB2, w67.x); ffma2(aB[7], vB2, w67.y);
            }

            #pragma unroll
            for (int p = 0; p < 8; p++) {
                float g0, g1;
                unpack2(gelu2(aA[p]), g0, g1);
                s_feat[(2*p)  *FD*FDP + fyA*FDP + fxA] = okA ? g0 : 0.f;
                s_feat[(2*p+1)*FD*FDP + fyA*FDP + fxA] = okA ? g1 : 0.f;
                unpack2(gelu2(aB[p]), g0, g1);
                s_feat[(2*p)  *FD*FDP + fyB*FDP + fxB] = okB ? g0 : 0.f;
                s_feat[(2*p+1)*FD*FDP + fyB*FDP + fxB] = okB ? g1 : 0.f;
            }
        }
    }
    __syncthreads();

    // ---- phase 3: conv2 (active taps) + bilinear; f32x2 x-pairs ----
    const int x0  = (tid & 7) * 4;
    const int row = tid >> 3;
    const float* img = pm25 + (size_t)b * Hn * Wn;
    float* s_wdup = s_in;    // dead region; [j][c]{wdy,wdy,wdx,wdx} = 576 floats

    float acc[4] = {0.f, 0.f, 0.f, 0.f};

    for (int k = 0; k < 9; k++) {
        const float wkv = s_wk[k];
        if (wkv == 0.0f) continue;          // uniform across grid, value-exact
        const int kdy = k / 3 - 1, kdx = k - (k/3)*3 - 1;

        __syncthreads();
        for (int i = tid; i < 144; i += 256) {
            const int c = i / 9, j = i - c * 9;
            const float wy = __ldg(&w2[(size_t)(2*k)    *144 + c*9 + j]);
            const float wx = __ldg(&w2[(size_t)(2*k + 1)*144 + c*9 + j]);
            float* p = &s_wdup[(j*16 + c)*4];
            p[0] = wy; p[1] = wy; p[2] = wx; p[3] = wx;
        }
        __syncthreads();

        const float bdy = s_b2[2*k], bdx = s_b2[2*k + 1];
        ull ady0 = pack2(bdy, bdy), ady1 = ady0;
        ull adx0 = pack2(bdx, bdx), adx1 = adx0;

        #pragma unroll
        for (int c = 0; c < 16; c++) {
            const float* fb = s_feat + c*FD*FDP + row*FDP + x0;
            ull P[3][5];
            #pragma unroll
            for (int ky = 0; ky < 3; ky++) {
                const float* rp = fb + ky*FDP;
                const ulonglong2 q0 = *(const ulonglong2*)rp;   // {f0,f1},{f2,f3}
                const ull        q1 = *(const ull*)(rp + 4);    // {f4,f5}
                float f0, f1, f2, f3, f4, f5;
                unpack2(q0.x, f0, f1);
                unpack2(q0.y, f2, f3);
                unpack2(q1,   f4, f5);
                P[ky][0] = q0.x;
                P[ky][2] = q0.y;
                P[ky][4] = q1;
                P[ky][1] = pack2(f1, f2);
                P[ky][3] = pack2(f3, f4);
            }
            #pragma unroll
            for (int ky = 0; ky < 3; ky++) {
                #pragma unroll
                for (int kx = 0; kx < 3; kx++) {
                    const int jj = ky*3 + kx;
                    const ulonglong2 wv = *(const ulonglong2*)&s_wdup[(jj*16 + c)*4];
                    ffma2(ady0, P[ky][kx],     wv.x);
                    ffma2(ady1, P[ky][kx + 2], wv.x);
                    ffma2(adx0, P[ky][kx],     wv.y);
                    ffma2(adx1, P[ky][kx + 2], wv.y);
                }
            }
        }

        float dyv[4], dxv[4];
        unpack2(ady0, dyv[0], dyv[1]); unpack2(ady1, dyv[2], dyv[3]);
        unpack2(adx0, dxv[0], dxv[1]); unpack2(adx1, dxv[2], dxv[3]);

        #pragma unroll
        for (int i = 0; i < 4; i++) {
            const int gy = ty0 + row;
            const int gx = tx0 + x0 + i;
            const float py = (float)(gy + kdy) + dyv[i];
            const float px = (float)(gx + kdx) + dxv[i];
            const float y0f = floorf(py), x0f = floorf(px);
            const float wy = py - y0f, wx = px - x0f;
            const int yy0 = (int)y0f, xx0 = (int)x0f;
            const int yy1 = yy0 + 1,  xx1 = xx0 + 1;
            const bool okY0 = (yy0 >= 0) & (yy0 < Hn);
            const bool okY1 = (yy1 >= 0) & (yy1 < Hn);
            const bool okX0 = (xx0 >= 0) & (xx0 < Wn);
            const bool okX1 = (xx1 >= 0) & (xx1 < Wn);
            const float v00 = (okY0 & okX0) ? __ldg(img + (size_t)yy0*Wn + xx0) : 0.f;
            const float v01 = (okY0 & okX1) ? __ldg(img + (size_t)yy0*Wn + xx1) : 0.f;
            const float v10 = (okY1 & okX0) ? __ldg(img + (size_t)yy1*Wn + xx0) : 0.f;
            const float v11 = (okY1 & okX1) ? __ldg(img + (size_t)yy1*Wn + xx1) : 0.f;
            const float s = v00*(1.f - wy)*(1.f - wx) + v01*(1.f - wy)*wx
                          + v10*wy*(1.f - wx)         + v11*wy*wx;
            acc[i] = fmaf(wkv, s, acc[i]);
        }
    }

    float4 o4; o4.x = acc[0]; o4.y = acc[1]; o4.z = acc[2]; o4.w = acc[3];
    *(float4*)&out[(size_t)b * Hn * Wn + (size_t)(ty0 + row) * Wn + (tx0 + x0)] = o4;
}

extern "C" void kernel_launch(void* const* d_in, const int* in_sizes, int n_in,
                              void* d_out, int out_size)
{
    const float* pm25 = (const float*)d_in[0];
    const float* wind = (const float*)d_in[1];
    const float* topo = (const float*)d_in[2];
    const float* w1   = (const float*)d_in[3];
    const float* b1   = (const float*)d_in[4];
    const float* w2   = (const float*)d_in[5];
    const float* b2   = (const float*)d_in[6];
    const float* wk   = (const float*)d_in[7];
    float* out = (float*)d_out;

    const size_t smem_bytes = (size_t)SMEM_FLOATS * sizeof(float);
    cudaFuncSetAttribute(fused_residual_advection,
                         cudaFuncAttributeMaxDynamicSharedMemorySize,
                         (int)smem_bytes);

    dim3 grid(Wn / TILE, Hn / TILE, Bn);
    fused_residual_advection<<<grid, 256, smem_bytes>>>(
        pm25, wind, topo, w1, b1, w2, b2, wk, out);
}

// round 7
// speedup vs baseline: 1.5537x; 1.0219x over previous
#include <cuda_runtime.h>
#include <cuda_fp16.h>
#include <math.h>

// Fixed problem shape: B=16, H=W=512
#define Bn 16
#define Hn 512
#define Wn 512
#define TILE 32
#define FD  34       // feat rows/cols (halo 1)
#define FDPH 40      // feat pitch in halves (80B rows -> 16B-aligned rows)
#define ID  36       // input tile with halo 2

// smem floats: s_in 3888 | feat(fp16) 16*34*40/2 = 10880 | w1t 432 | b1 16 | b2 18 | wk 9
#define SMEM_FLOATS (3*ID*ID + (16*FD*FDPH)/2 + 432 + 16 + 18 + 9)

typedef unsigned long long ull;

__device__ __forceinline__ ull pack2(float lo, float hi) {
    ull r; asm("mov.b64 %0, {%1, %2};" : "=l"(r) : "f"(lo), "f"(hi)); return r;
}
__device__ __forceinline__ void unpack2(ull v, float& lo, float& hi) {
    asm("mov.b64 {%0, %1}, %2;" : "=f"(lo), "=f"(hi) : "l"(v));
}
__device__ __forceinline__ void ffma2(ull& d, ull a, ull b) {
    asm("fma.rn.f32x2 %0, %1, %2, %0;" : "+l"(d) : "l"(a), "l"(b));
}
__device__ __forceinline__ ull fma2v(ull a, ull b, ull c) {
    ull r; asm("fma.rn.f32x2 %0, %1, %2, %3;" : "=l"(r) : "l"(a), "l"(b), "l"(c)); return r;
}
__device__ __forceinline__ ull mul2(ull a, ull b) {
    ull r; asm("mul.rn.f32x2 %0, %1, %2;" : "=l"(r) : "l"(a), "l"(b)); return r;
}
__device__ __forceinline__ ull add2(ull a, ull b) {
    ull r; asm("add.rn.f32x2 %0, %1, %2;" : "=l"(r) : "l"(a), "l"(b)); return r;
}

// GELU on 2 packed fp32 lanes; Phi via A&S 26.2.17 (|err| < 7.5e-8).
__device__ __forceinline__ ull gelu2(ull x2) {
    ull a2;  asm("and.b64 %0, %1, %2;" : "=l"(a2) : "l"(x2), "l"(0x7FFFFFFF7FFFFFFFULL));
    ull d2 = fma2v(pack2(0.2316419f, 0.2316419f), a2, pack2(1.0f, 1.0f));
    float dlo, dhi; unpack2(d2, dlo, dhi);
    float tlo, thi;
    asm("rcp.approx.f32 %0, %1;" : "=f"(tlo) : "f"(dlo));
    asm("rcp.approx.f32 %0, %1;" : "=f"(thi) : "f"(dhi));
    ull t2 = pack2(tlo, thi);
    ull m2 = mul2(a2, a2);
    ull g2 = mul2(m2, pack2(-0.72134752f, -0.72134752f));
    float glo, ghi; unpack2(g2, glo, ghi);
    float elo, ehi;
    asm("ex2.approx.f32 %0, %1;" : "=f"(elo) : "f"(glo));
    asm("ex2.approx.f32 %0, %1;" : "=f"(ehi) : "f"(ghi));
    ull e2 = pack2(elo, ehi);
    ull u = fma2v(pack2( 0.53070279f,  0.53070279f), t2, pack2(-0.72657601f, -0.72657601f));
    u = fma2v(u, t2, pack2( 0.71070696f,  0.71070696f));
    u = fma2v(u, t2, pack2(-0.14224837f, -0.14224837f));
    u = fma2v(u, t2, pack2( 0.12741480f,  0.12741480f));
    u = mul2(u, t2);
    ull q2 = mul2(e2, u);
    ull h2 = fma2v(q2, pack2(-1.0f, -1.0f), pack2(0.5f, 0.5f));
    ull s2;  asm("and.b64 %0, %1, %2;" : "=l"(s2) : "l"(x2), "l"(0x8000000080000000ULL));
    ull sh2; asm("or.b64  %0, %1, %2;" : "=l"(sh2) : "l"(s2), "l"(h2));
    ull phi2 = add2(sh2, pack2(0.5f, 0.5f));
    return mul2(x2, phi2);
}

__global__ __launch_bounds__(256, 3)
void fused_residual_advection(const float* __restrict__ pm25,
                              const float* __restrict__ wind,
                              const float* __restrict__ topo,
                              const float* __restrict__ w1,
                              const float* __restrict__ b1,
                              const float* __restrict__ w2,
                              const float* __restrict__ b2,
                              const float* __restrict__ wk,
                              float* __restrict__ out)
{
    extern __shared__ float smem[];
    float*  s_in     = smem;                         // [3][36][36]; phase3: dup-w table
    __half* s_feat_h = (__half*)(s_in + 3*ID*ID);    // [16][34][40] halves
    float*  s_w1t    = s_in + 3*ID*ID + (16*FD*FDPH)/2;  // [27][16]
    float*  s_b1     = s_w1t + 432;
    float*  s_b2     = s_b1 + 16;
    float*  s_wk     = s_b2 + 18;

    const int tid = threadIdx.x;
    const int b   = blockIdx.z;
    const int ty0 = blockIdx.y * TILE;
    const int tx0 = blockIdx.x * TILE;

    for (int i = tid; i < 432; i += 256) {
        int o = i / 27, j = i - o * 27;
        s_w1t[j*16 + o] = w1[i];
    }
    if (tid < 16) s_b1[tid] = b1[tid];
    else if (tid >= 32 && tid < 50) s_b2[tid - 32] = b2[tid - 32];
    else if (tid >= 64 && tid < 73) s_wk[tid - 64] = wk[tid - 64];

    const int gy0 = ty0 - 2, gx0 = tx0 - 2;
    const float* wind0 = wind + (size_t)b * 2 * Hn * Wn;
    const float* wind1 = wind0 + Hn * Wn;
    const float* topob = topo + (size_t)b * Hn * Wn;
    for (int i = tid; i < ID*ID; i += 256) {
        int ly = i / ID, lx = i - ly * ID;
        int gy = gy0 + ly, gx = gx0 + lx;
        bool ok = (gy >= 0) & (gy < Hn) & (gx >= 0) & (gx < Wn);
        size_t gidx = (size_t)gy * Wn + gx;
        s_in[0*ID*ID + i] = ok ? __ldg(wind0 + gidx) : 0.f;
        s_in[1*ID*ID + i] = ok ? __ldg(wind1 + gidx) : 0.f;
        s_in[2*ID*ID + i] = ok ? __ldg(topob + gidx) : 0.f;
    }
    __syncthreads();

    // ---- phase 2: conv1 + GELU -> fp16 feat; 1 pixel/iter (low reg pressure) ----
    {
        ull b1p[8];
        #pragma unroll
        for (int p = 0; p < 8; p++) b1p[p] = pack2(s_b1[2*p], s_b1[2*p + 1]);

        for (int idx = tid; idx < FD*FD; idx += 256) {
            const int fy = idx / FD, fx = idx - fy * FD;
            const bool ok = ((unsigned)(ty0 - 1 + fy) < Hn) & ((unsigned)(tx0 - 1 + fx) < Wn);
            const int base = fy*ID + fx;

            ull a[8];
            #pragma unroll
            for (int p = 0; p < 8; p++) a[p] = b1p[p];

            #pragma unroll
            for (int j = 0; j < 27; j++) {
                const int c  = j / 9;
                const int r9 = j - c * 9;
                const int ky = r9 / 3, kx = r9 - ky * 3;
                const float v = s_in[c*ID*ID + base + ky*ID + kx];
                const ull v2 = pack2(v, v);
                const ulonglong2* wp = (const ulonglong2*)&s_w1t[j*16];
                const ulonglong2 w01 = wp[0], w23 = wp[1], w45 = wp[2], w67 = wp[3];
                ffma2(a[0], v2, w01.x); ffma2(a[1], v2, w01.y);
                ffma2(a[2], v2, w23.x); ffma2(a[3], v2, w23.y);
                ffma2(a[4], v2, w45.x); ffma2(a[5], v2, w45.y);
                ffma2(a[6], v2, w67.x); ffma2(a[7], v2, w67.y);
            }

            const int po = fy*FDPH + fx;
            #pragma unroll
            for (int p = 0; p < 8; p++) {
                float g0, g1;
                unpack2(gelu2(a[p]), g0, g1);
                s_feat_h[(2*p)  *FD*FDPH + po] = __float2half_rn(ok ? g0 : 0.f);
                s_feat_h[(2*p+1)*FD*FDPH + po] = __float2half_rn(ok ? g1 : 0.f);
            }
        }
    }
    __syncthreads();

    // ---- phase 3: conv2 (active taps) + bilinear; f32x2 x-pairs, fp16 feat ----
    const int x0  = (tid & 7) * 4;
    const int row = tid >> 3;
    const float* img = pm25 + (size_t)b * Hn * Wn;
    float* s_wdup = s_in;    // dead region; [j][c]{wdy,wdy,wdx,wdx} = 576 floats

    float acc[4] = {0.f, 0.f, 0.f, 0.f};

    for (int k = 0; k < 9; k++) {
        const float wkv = s_wk[k];
        if (wkv == 0.0f) continue;          // uniform across grid, value-exact
        const int kdy = k / 3 - 1, kdx = k - (k/3)*3 - 1;

        __syncthreads();
        for (int i = tid; i < 144; i += 256) {
            const int c = i / 9, j = i - c * 9;
            const float wy = __ldg(&w2[(size_t)(2*k)    *144 + c*9 + j]);
            const float wx = __ldg(&w2[(size_t)(2*k + 1)*144 + c*9 + j]);
            float* p = &s_wdup[(j*16 + c)*4];
            p[0] = wy; p[1] = wy; p[2] = wx; p[3] = wx;
        }
        __syncthreads();

        const float bdy = s_b2[2*k], bdx = s_b2[2*k + 1];
        ull ady0 = pack2(bdy, bdy), ady1 = ady0;
        ull adx0 = pack2(bdx, bdx), adx1 = adx0;

        #pragma unroll
        for (int c = 0; c < 16; c++) {
            const __half* fb = s_feat_h + c*FD*FDPH + row*FDPH + x0;
            #pragma unroll
            for (int ky = 0; ky < 3; ky++) {
                const __half* rp = fb + ky*FDPH;
                const __half2 h01 = *(const __half2*)(rp);
                const __half2 h23 = *(const __half2*)(rp + 2);
                const __half2 h45 = *(const __half2*)(rp + 4);
                const float2 e0 = __half22float2(h01);
                const float2 e1 = __half22float2(h23);
                const float2 e2 = __half22float2(h45);
                const ull P0 = pack2(e0.x, e0.y);
                const ull P1 = pack2(e0.y, e1.x);
                const ull P2 = pack2(e1.x, e1.y);
                const ull P3 = pack2(e1.y, e2.x);
                const ull P4 = pack2(e2.x, e2.y);

                const ulonglong2 wv0 = *(const ulonglong2*)&s_wdup[((ky*3+0)*16 + c)*4];
                const ulonglong2 wv1 = *(const ulonglong2*)&s_wdup[((ky*3+1)*16 + c)*4];
                const ulonglong2 wv2 = *(const ulonglong2*)&s_wdup[((ky*3+2)*16 + c)*4];
                ffma2(ady0, P0, wv0.x); ffma2(ady1, P2, wv0.x);
                ffma2(adx0, P0, wv0.y); ffma2(adx1, P2, wv0.y);
                ffma2(ady0, P1, wv1.x); ffma2(ady1, P3, wv1.x);
                ffma2(adx0, P1, wv1.y); ffma2(adx1, P3, wv1.y);
                ffma2(ady0, P2, wv2.x); ffma2(ady1, P4, wv2.x);
                ffma2(adx0, P2, wv2.y); ffma2(adx1, P4, wv2.y);
            }
        }

        float dyv[4], dxv[4];
        unpack2(ady0, dyv[0], dyv[1]); unpack2(ady1, dyv[2], dyv[3]);
        unpack2(adx0, dxv[0], dxv[1]); unpack2(adx1, dxv[2], dxv[3]);

        #pragma unroll
        for (int i = 0; i < 4; i++) {
            const int gy = ty0 + row;
            const int gx = tx0 + x0 + i;
            const float py = (float)(gy + kdy) + dyv[i];
            const float px = (float)(gx + kdx) + dxv[i];
            const float y0f = floorf(py), x0f = floorf(px);
            const float wy = py - y0f, wx = px - x0f;
            const int yy0 = (int)y0f, xx0 = (int)x0f;
            const int yy1 = yy0 + 1,  xx1 = xx0 + 1;
            const bool okY0 = (yy0 >= 0) & (yy0 < Hn);
            const bool okY1 = (yy1 >= 0) & (yy1 < Hn);
            const bool okX0 = (xx0 >= 0) & (xx0 < Wn);
            const bool okX1 = (xx1 >= 0) & (xx1 < Wn);
            const float v00 = (okY0 & okX0) ? __ldg(img + (size_t)yy0*Wn + xx0) : 0.f;
            const float v01 = (okY0 & okX1) ? __ldg(img + (size_t)yy0*Wn + xx1) : 0.f;
            const float v10 = (okY1 & okX0) ? __ldg(img + (size_t)yy1*Wn + xx0) : 0.f;
            const float v11 = (okY1 & okX1) ? __ldg(img + (size_t)yy1*Wn + xx1) : 0.f;
            const float s = v00*(1.f - wy)*(1.f - wx) + v01*(1.f - wy)*wx
                          + v10*wy*(1.f - wx)         + v11*wy*wx;
            acc[i] = fmaf(wkv, s, acc[i]);
        }
    }

    float4 o4; o4.x = acc[0]; o4.y = acc[1]; o4.z = acc[2]; o4.w = acc[3];
    *(float4*)&out[(size_t)b * Hn * Wn + (size_t)(ty0 + row) * Wn + (tx0 + x0)] = o4;
}

extern "C" void kernel_launch(void* const* d_in, const int* in_sizes, int n_in,
                              void* d_out, int out_size)
{
    const float* pm25 = (const float*)d_in[0];
    const float* wind = (const float*)d_in[1];
    const float* topo = (const float*)d_in[2];
    const float* w1   = (const float*)d_in[3];
    const float* b1   = (const float*)d_in[4];
    const float* w2   = (const float*)d_in[5];
    const float* b2   = (const float*)d_in[6];
    const float* wk   = (const float*)d_in[7];
    float* out = (float*)d_out;

    const size_t smem_bytes = (size_t)SMEM_FLOATS * sizeof(float);
    cudaFuncSetAttribute(fused_residual_advection,
                         cudaFuncAttributeMaxDynamicSharedMemorySize,
                         (int)smem_bytes);

    dim3 grid(Wn / TILE, Hn / TILE, Bn);
    fused_residual_advection<<<grid, 256, smem_bytes>>>(
        pm25, wind, topo, w1, b1, w2, b2, wk, out);
}

// round 8
// speedup vs baseline: 1.6505x; 1.0622x over previous
#include <cuda_runtime.h>
#include <cuda_fp16.h>
#include <math.h>

// Fixed problem shape: B=16, H=W=512
#define Bn 16
#define Hn 512
#define Wn 512
#define TILE 32
#define FD  34       // feat rows/cols (halo 1)
#define FDPH 40      // feat pitch in halves (80B rows, 8B-aligned accesses)
#define ID  36       // input tile with halo 2

// smem floats: s_in 3888 | feat(fp16) 10880 | w1t 432 | b1 16 | b2 18 | wk 9
#define SMEM_FLOATS (3*ID*ID + (16*FD*FDPH)/2 + 432 + 16 + 18 + 9)

typedef unsigned long long ull;

__device__ __forceinline__ ull pack2(float lo, float hi) {
    ull r; asm("mov.b64 %0, {%1, %2};" : "=l"(r) : "f"(lo), "f"(hi)); return r;
}
__device__ __forceinline__ void unpack2(ull v, float& lo, float& hi) {
    asm("mov.b64 {%0, %1}, %2;" : "=f"(lo), "=f"(hi) : "l"(v));
}
__device__ __forceinline__ void ffma2(ull& d, ull a, ull b) {
    asm("fma.rn.f32x2 %0, %1, %2, %0;" : "+l"(d) : "l"(a), "l"(b));
}
__device__ __forceinline__ ull fma2v(ull a, ull b, ull c) {
    ull r; asm("fma.rn.f32x2 %0, %1, %2, %3;" : "=l"(r) : "l"(a), "l"(b), "l"(c)); return r;
}
__device__ __forceinline__ ull mul2(ull a, ull b) {
    ull r; asm("mul.rn.f32x2 %0, %1, %2;" : "=l"(r) : "l"(a), "l"(b)); return r;
}
__device__ __forceinline__ ull add2(ull a, ull b) {
    ull r; asm("add.rn.f32x2 %0, %1, %2;" : "=l"(r) : "l"(a), "l"(b)); return r;
}

// GELU on 2 packed fp32 lanes; Phi via A&S 26.2.17 (|err| < 7.5e-8).
__device__ __forceinline__ ull gelu2(ull x2) {
    ull a2;  asm("and.b64 %0, %1, %2;" : "=l"(a2) : "l"(x2), "l"(0x7FFFFFFF7FFFFFFFULL));
    ull d2 = fma2v(pack2(0.2316419f, 0.2316419f), a2, pack2(1.0f, 1.0f));
    float dlo, dhi; unpack2(d2, dlo, dhi);
    float tlo, thi;
    asm("rcp.approx.f32 %0, %1;" : "=f"(tlo) : "f"(dlo));
    asm("rcp.approx.f32 %0, %1;" : "=f"(thi) : "f"(dhi));
    ull t2 = pack2(tlo, thi);
    ull m2 = mul2(a2, a2);
    ull g2 = mul2(m2, pack2(-0.72134752f, -0.72134752f));
    float glo, ghi; unpack2(g2, glo, ghi);
    float elo, ehi;
    asm("ex2.approx.f32 %0, %1;" : "=f"(elo) : "f"(glo));
    asm("ex2.approx.f32 %0, %1;" : "=f"(ehi) : "f"(ghi));
    ull e2 = pack2(elo, ehi);
    ull u = fma2v(pack2( 0.53070279f,  0.53070279f), t2, pack2(-0.72657601f, -0.72657601f));
    u = fma2v(u, t2, pack2( 0.71070696f,  0.71070696f));
    u = fma2v(u, t2, pack2(-0.14224837f, -0.14224837f));
    u = fma2v(u, t2, pack2( 0.12741480f,  0.12741480f));
    u = mul2(u, t2);
    ull q2 = mul2(e2, u);
    ull h2 = fma2v(q2, pack2(-1.0f, -1.0f), pack2(0.5f, 0.5f));
    ull s2;  asm("and.b64 %0, %1, %2;" : "=l"(s2) : "l"(x2), "l"(0x8000000080000000ULL));
    ull sh2; asm("or.b64  %0, %1, %2;" : "=l"(sh2) : "l"(s2), "l"(h2));
    ull phi2 = add2(sh2, pack2(0.5f, 0.5f));
    return mul2(x2, phi2);
}

__global__ __launch_bounds__(256, 3)
void fused_residual_advection(const float* __restrict__ pm25,
                              const float* __restrict__ wind,
                              const float* __restrict__ topo,
                              const float* __restrict__ w1,
                              const float* __restrict__ b1,
                              const float* __restrict__ w2,
                              const float* __restrict__ b2,
                              const float* __restrict__ wk,
                              float* __restrict__ out)
{
    extern __shared__ float smem[];
    float*  s_in     = smem;                             // [3][36][36]; phase3: dup-w table
    __half* s_feat_h = (__half*)(s_in + 3*ID*ID);        // [16][34][40] halves
    float*  s_w1t    = s_in + 3*ID*ID + (16*FD*FDPH)/2;  // [27][16]
    float*  s_b1     = s_w1t + 432;
    float*  s_b2     = s_b1 + 16;
    float*  s_wk     = s_b2 + 18;

    const int tid = threadIdx.x;
    const int b   = blockIdx.z;
    const int ty0 = blockIdx.y * TILE;
    const int tx0 = blockIdx.x * TILE;

    for (int i = tid; i < 432; i += 256) {
        int o = i / 27, j = i - o * 27;
        s_w1t[j*16 + o] = w1[i];
    }
    if (tid < 16) s_b1[tid] = b1[tid];
    else if (tid >= 32 && tid < 50) s_b2[tid - 32] = b2[tid - 32];
    else if (tid >= 64 && tid < 73) s_wk[tid - 64] = wk[tid - 64];

    const int gy0 = ty0 - 2, gx0 = tx0 - 2;
    const float* wind0 = wind + (size_t)b * 2 * Hn * Wn;
    const float* wind1 = wind0 + Hn * Wn;
    const float* topob = topo + (size_t)b * Hn * Wn;
    for (int i = tid; i < ID*ID; i += 256) {
        int ly = i / ID, lx = i - ly * ID;
        int gy = gy0 + ly, gx = gx0 + lx;
        bool ok = (gy >= 0) & (gy < Hn) & (gx >= 0) & (gx < Wn);
        size_t gidx = (size_t)gy * Wn + gx;
        s_in[0*ID*ID + i] = ok ? __ldg(wind0 + gidx) : 0.f;
        s_in[1*ID*ID + i] = ok ? __ldg(wind1 + gidx) : 0.f;
        s_in[2*ID*ID + i] = ok ? __ldg(topob + gidx) : 0.f;
    }
    __syncthreads();

    // ---- phase 2: conv1 + GELU -> fp16 feat ----
    // 2 pixels (A,B) x channel-halves: weight LDS amortized 2x, acc regs stay at 16.
    {
        ull b1p[8];
        #pragma unroll
        for (int p = 0; p < 8; p++) b1p[p] = pack2(s_b1[2*p], s_b1[2*p + 1]);

        const int half = (FD*FD)/2;   // 578
        for (int idx = tid; idx < half; idx += 256) {
            const int idx2 = idx + half;
            const int fyA = idx  / FD, fxA = idx  - fyA * FD;
            const int fyB = idx2 / FD, fxB = idx2 - fyB * FD;
            const bool okA = ((unsigned)(ty0 - 1 + fyA) < Hn) & ((unsigned)(tx0 - 1 + fxA) < Wn);
            const bool okB = ((unsigned)(ty0 - 1 + fyB) < Hn) & ((unsigned)(tx0 - 1 + fxB) < Wn);
            const int baseA = fyA*ID + fxA, baseB = fyB*ID + fxB;
            const int poA = fyA*FDPH + fxA, poB = fyB*FDPH + fxB;

            #pragma unroll
            for (int h = 0; h < 2; h++) {
                ull aA[4], aB[4];
                #pragma unroll
                for (int p = 0; p < 4; p++) { aA[p] = b1p[4*h + p]; aB[p] = b1p[4*h + p]; }

                #pragma unroll
                for (int j = 0; j < 27; j++) {
                    const int c  = j / 9;
                    const int r9 = j - c * 9;
                    const int ky = r9 / 3, kx = r9 - ky * 3;
                    const float vA = s_in[c*ID*ID + baseA + ky*ID + kx];
                    const float vB = s_in[c*ID*ID + baseB + ky*ID + kx];
                    const ull vA2 = pack2(vA, vA);
                    const ull vB2 = pack2(vB, vB);
                    const ulonglong2* wp = (const ulonglong2*)&s_w1t[j*16 + h*8];
                    const ulonglong2 w01 = wp[0], w23 = wp[1];
                    ffma2(aA[0], vA2, w01.x); ffma2(aA[1], vA2, w01.y);
                    ffma2(aA[2], vA2, w23.x); ffma2(aA[3], vA2, w23.y);
                    ffma2(aB[0], vB2, w01.x); ffma2(aB[1], vB2, w01.y);
                    ffma2(aB[2], vB2, w23.x); ffma2(aB[3], vB2, w23.y);
                }

                #pragma unroll
                for (int p = 0; p < 4; p++) {
                    const int ch = 8*h + 2*p;
                    float g0, g1;
                    unpack2(gelu2(aA[p]), g0, g1);
                    s_feat_h[ch    *FD*FDPH + poA] = __float2half_rn(okA ? g0 : 0.f);
                    s_feat_h[(ch+1)*FD*FDPH + poA] = __float2half_rn(okA ? g1 : 0.f);
                    unpack2(gelu2(aB[p]), g0, g1);
                    s_feat_h[ch    *FD*FDPH + poB] = __float2half_rn(okB ? g0 : 0.f);
                    s_feat_h[(ch+1)*FD*FDPH + poB] = __float2half_rn(okB ? g1 : 0.f);
                }
            }
        }
    }
    __syncthreads();

    // ---- phase 3: conv2 (active taps) + bilinear; f32x2 x-pairs, fp16 feat ----
    const int x0  = (tid & 7) * 4;
    const int row = tid >> 3;
    const float* img = pm25 + (size_t)b * Hn * Wn;
    float* s_wdup = s_in;    // dead region; [j][c]{wdy,wdy,wdx,wdx} = 576 floats

    float acc[4] = {0.f, 0.f, 0.f, 0.f};

    for (int k = 0; k < 9; k++) {
        const float wkv = s_wk[k];
        if (wkv == 0.0f) continue;          // uniform across block, value-exact
        const int kdy = k / 3 - 1, kdx = k - (k/3)*3 - 1;

        __syncthreads();
        for (int i = tid; i < 144; i += 256) {
            const int c = i / 9, j = i - c * 9;
            const float wy = __ldg(&w2[(size_t)(2*k)    *144 + c*9 + j]);
            const float wx = __ldg(&w2[(size_t)(2*k + 1)*144 + c*9 + j]);
            float* p = &s_wdup[(j*16 + c)*4];
            p[0] = wy; p[1] = wy; p[2] = wx; p[3] = wx;
        }
        __syncthreads();

        const float bdy = s_b2[2*k], bdx = s_b2[2*k + 1];
        ull ady0 = pack2(bdy, bdy), ady1 = ady0;
        ull adx0 = pack2(bdx, bdx), adx1 = adx0;

        #pragma unroll
        for (int c = 0; c < 16; c++) {
            const __half* fb = s_feat_h + c*FD*FDPH + row*FDPH + x0;
            #pragma unroll
            for (int ky = 0; ky < 3; ky++) {
                const __half* rp = fb + ky*FDPH;
                const uint2 q = *(const uint2*)(rp);              // 8B: h0..h3
                const __half2 h01 = *(const __half2*)&q.x;
                const __half2 h23 = *(const __half2*)&q.y;
                const __half2 h45 = *(const __half2*)(rp + 4);    // 4B: h4,h5
                const float2 e0 = __half22float2(h01);
                const float2 e1 = __half22float2(h23);
                const float2 e2 = __half22float2(h45);
                const ull P0 = pack2(e0.x, e0.y);
                const ull P1 = pack2(e0.y, e1.x);
                const ull P2 = pack2(e1.x, e1.y);
                const ull P3 = pack2(e1.y, e2.x);
                const ull P4 = pack2(e2.x, e2.y);

                const ulonglong2 wv0 = *(const ulonglong2*)&s_wdup[((ky*3+0)*16 + c)*4];
                const ulonglong2 wv1 = *(const ulonglong2*)&s_wdup[((ky*3+1)*16 + c)*4];
                const ulonglong2 wv2 = *(const ulonglong2*)&s_wdup[((ky*3+2)*16 + c)*4];
                ffma2(ady0, P0, wv0.x); ffma2(ady1, P2, wv0.x);
                ffma2(adx0, P0, wv0.y); ffma2(adx1, P2, wv0.y);
                ffma2(ady0, P1, wv1.x); ffma2(ady1, P3, wv1.x);
                ffma2(adx0, P1, wv1.y); ffma2(adx1, P3, wv1.y);
                ffma2(ady0, P2, wv2.x); ffma2(ady1, P4, wv2.x);
                ffma2(adx0, P2, wv2.y); ffma2(adx1, P4, wv2.y);
            }
        }

        float dyv[4], dxv[4];
        unpack2(ady0, dyv[0], dyv[1]); unpack2(ady1, dyv[2], dyv[3]);
        unpack2(adx0, dxv[0], dxv[1]); unpack2(adx1, dxv[2], dxv[3]);

        #pragma unroll
        for (int i = 0; i < 4; i++) {
            const int gy = ty0 + row;
            const int gx = tx0 + x0 + i;
            const float py = (float)(gy + kdy) + dyv[i];
            const float px = (float)(gx + kdx) + dxv[i];
            const float y0f = floorf(py), x0f = floorf(px);
            const float wy = py - y0f, wx = px - x0f;
            const int yy0 = (int)y0f, xx0 = (int)x0f;
            const int yy1 = yy0 + 1,  xx1 = xx0 + 1;
            const bool okY0 = (yy0 >= 0) & (yy0 < Hn);
            const bool okY1 = (yy1 >= 0) & (yy1 < Hn);
            const bool okX0 = (xx0 >= 0) & (xx0 < Wn);
            const bool okX1 = (xx1 >= 0) & (xx1 < Wn);
            const float v00 = (okY0 & okX0) ? __ldg(img + (size_t)yy0*Wn + xx0) : 0.f;
            const float v01 = (okY0 & okX1) ? __ldg(img + (size_t)yy0*Wn + xx1) : 0.f;
            const float v10 = (okY1 & okX0) ? __ldg(img + (size_t)yy1*Wn + xx0) : 0.f;
            const float v11 = (okY1 & okX1) ? __ldg(img + (size_t)yy1*Wn + xx1) : 0.f;
            const float s = v00*(1.f - wy)*(1.f - wx) + v01*(1.f - wy)*wx
                          + v10*wy*(1.f - wx)         + v11*wy*wx;
            acc[i] = fmaf(wkv, s, acc[i]);
        }
    }

    float4 o4; o4.x = acc[0]; o4.y = acc[1]; o4.z = acc[2]; o4.w = acc[3];
    *(float4*)&out[(size_t)b * Hn * Wn + (size_t)(ty0 + row) * Wn + (tx0 + x0)] = o4;
}

extern "C" void kernel_launch(void* const* d_in, const int* in_sizes, int n_in,
                              void* d_out, int out_size)
{
    const float* pm25 = (const float*)d_in[0];
    const float* wind = (const float*)d_in[1];
    const float* topo = (const float*)d_in[2];
    const float* w1   = (const float*)d_in[3];
    const float* b1   = (const float*)d_in[4];
    const float* w2   = (const float*)d_in[5];
    const float* b2   = (const float*)d_in[6];
    const float* wk   = (const float*)d_in[7];
    float* out = (float*)d_out;

    const size_t smem_bytes = (size_t)SMEM_FLOATS * sizeof(float);
    cudaFuncSetAttribute(fused_residual_advection,
                         cudaFuncAttributeMaxDynamicSharedMemorySize,
                         (int)smem_bytes);

    dim3 grid(Wn / TILE, Hn / TILE, Bn);
    fused_residual_advection<<<grid, 256, smem_bytes>>>(
        pm25, wind, topo, w1, b1, w2, b2, wk, out);
}

// round 9
// speedup vs baseline: 1.6797x; 1.0177x over previous
#include <cuda_runtime.h>
#include <cuda_fp16.h>
#include <math.h>

// Fixed problem shape: B=16, H=W=512
#define Bn 16
#define Hn 512
#define Wn 512
#define TILE 32
#define FD  34       // feat rows/cols (halo 1)
#define FDPH 40      // feat pitch in halves (80B rows, 8B-aligned accesses)
#define ID  36       // input tile with halo 2

// smem floats: s_in 3888 | feat(fp16) 10880 | w1t 432 | b1 16 | b2 18 | wk 9
#define SMEM_FLOATS (3*ID*ID + (16*FD*FDPH)/2 + 432 + 16 + 18 + 9)

typedef unsigned long long ull;

__device__ __forceinline__ ull pack2(float lo, float hi) {
    ull r; asm("mov.b64 %0, {%1, %2};" : "=l"(r) : "f"(lo), "f"(hi)); return r;
}
__device__ __forceinline__ void unpack2(ull v, float& lo, float& hi) {
    asm("mov.b64 {%0, %1}, %2;" : "=f"(lo), "=f"(hi) : "l"(v));
}
__device__ __forceinline__ void ffma2(ull& d, ull a, ull b) {
    asm("fma.rn.f32x2 %0, %1, %2, %0;" : "+l"(d) : "l"(a), "l"(b));
}
__device__ __forceinline__ ull fma2v(ull a, ull b, ull c) {
    ull r; asm("fma.rn.f32x2 %0, %1, %2, %3;" : "=l"(r) : "l"(a), "l"(b), "l"(c)); return r;
}
__device__ __forceinline__ ull mul2(ull a, ull b) {
    ull r; asm("mul.rn.f32x2 %0, %1, %2;" : "=l"(r) : "l"(a), "l"(b)); return r;
}
__device__ __forceinline__ ull add2(ull a, ull b) {
    ull r; asm("add.rn.f32x2 %0, %1, %2;" : "=l"(r) : "l"(a), "l"(b)); return r;
}

// GELU on 2 packed fp32 lanes; Phi via A&S 26.2.17 (|err| < 7.5e-8).
__device__ __forceinline__ ull gelu2(ull x2) {
    ull a2;  asm("and.b64 %0, %1, %2;" : "=l"(a2) : "l"(x2), "l"(0x7FFFFFFF7FFFFFFFULL));
    ull d2 = fma2v(pack2(0.2316419f, 0.2316419f), a2, pack2(1.0f, 1.0f));
    float dlo, dhi; unpack2(d2, dlo, dhi);
    float tlo, thi;
    asm("rcp.approx.f32 %0, %1;" : "=f"(tlo) : "f"(dlo));
    asm("rcp.approx.f32 %0, %1;" : "=f"(thi) : "f"(dhi));
    ull t2 = pack2(tlo, thi);
    ull m2 = mul2(a2, a2);
    ull g2 = mul2(m2, pack2(-0.72134752f, -0.72134752f));
    float glo, ghi; unpack2(g2, glo, ghi);
    float elo, ehi;
    asm("ex2.approx.f32 %0, %1;" : "=f"(elo) : "f"(glo));
    asm("ex2.approx.f32 %0, %1;" : "=f"(ehi) : "f"(ghi));
    ull e2 = pack2(elo, ehi);
    ull u = fma2v(pack2( 0.53070279f,  0.53070279f), t2, pack2(-0.72657601f, -0.72657601f));
    u = fma2v(u, t2, pack2( 0.71070696f,  0.71070696f));
    u = fma2v(u, t2, pack2(-0.14224837f, -0.14224837f));
    u = fma2v(u, t2, pack2( 0.12741480f,  0.12741480f));
    u = mul2(u, t2);
    ull q2 = mul2(e2, u);
    ull h2 = fma2v(q2, pack2(-1.0f, -1.0f), pack2(0.5f, 0.5f));
    ull s2;  asm("and.b64 %0, %1, %2;" : "=l"(s2) : "l"(x2), "l"(0x8000000080000000ULL));
    ull sh2; asm("or.b64  %0, %1, %2;" : "=l"(sh2) : "l"(s2), "l"(h2));
    ull phi2 = add2(sh2, pack2(0.5f, 0.5f));
    return mul2(x2, phi2);
}

__global__ __launch_bounds__(256, 3)
void fused_residual_advection(const float* __restrict__ pm25,
                              const float* __restrict__ wind,
                              const float* __restrict__ topo,
                              const float* __restrict__ w1,
                              const float* __restrict__ b1,
                              const float* __restrict__ w2,
                              const float* __restrict__ b2,
                              const float* __restrict__ wk,
                              float* __restrict__ out)
{
    extern __shared__ float smem[];
    float*  s_in     = smem;                             // [3][36][36]; phase3: dup-w table
    __half* s_feat_h = (__half*)(s_in + 3*ID*ID);        // [16][34][40] halves
    float*  s_w1t    = s_in + 3*ID*ID + (16*FD*FDPH)/2;  // [27][16]
    float*  s_b1     = s_w1t + 432;
    float*  s_b2     = s_b1 + 16;
    float*  s_wk     = s_b2 + 18;

    const int tid = threadIdx.x;
    const int b   = blockIdx.z;
    const int ty0 = blockIdx.y * TILE;
    const int tx0 = blockIdx.x * TILE;

    for (int i = tid; i < 432; i += 256) {
        int o = i / 27, j = i - o * 27;
        s_w1t[j*16 + o] = w1[i];
    }
    if (tid < 16) s_b1[tid] = b1[tid];
    else if (tid >= 32 && tid < 50) s_b2[tid - 32] = b2[tid - 32];
    else if (tid >= 64 && tid < 73) s_wk[tid - 64] = wk[tid - 64];

    const int gy0 = ty0 - 2, gx0 = tx0 - 2;
    const float* wind0 = wind + (size_t)b * 2 * Hn * Wn;
    const float* wind1 = wind0 + Hn * Wn;
    const float* topob = topo + (size_t)b * Hn * Wn;
    for (int i = tid; i < ID*ID; i += 256) {
        int ly = i / ID, lx = i - ly * ID;
        int gy = gy0 + ly, gx = gx0 + lx;
        bool ok = (gy >= 0) & (gy < Hn) & (gx >= 0) & (gx < Wn);
        size_t gidx = (size_t)gy * Wn + gx;
        s_in[0*ID*ID + i] = ok ? __ldg(wind0 + gidx) : 0.f;
        s_in[1*ID*ID + i] = ok ? __ldg(wind1 + gidx) : 0.f;
        s_in[2*ID*ID + i] = ok ? __ldg(topob + gidx) : 0.f;
    }
    __syncthreads();

    // ---- phase 2: conv1 + GELU -> fp16 feat ----
    // ADJACENT pixel pairs (fx even, fx+1): shared 3x4x3 input window hoisted to
    // 36 regs (18 LDS.64), reused across both channel-halves; half2 feat stores.
    {
        ull b1p[8];
        #pragma unroll
        for (int p = 0; p < 8; p++) b1p[p] = pack2(s_b1[2*p], s_b1[2*p + 1]);

        const int npairs = (FD*FD)/2;   // 578; pair p -> linear pixels 2p, 2p+1
        for (int pi = tid; pi < npairs; pi += 256) {
            const int lin = 2*pi;
            const int fy = lin / FD, fx = lin - fy * FD;   // fx even, fx+1 <= 33
            const bool okA = ((unsigned)(ty0 - 1 + fy) < Hn) & ((unsigned)(tx0 - 1 + fx)     < Wn);
            const bool okB = ((unsigned)(ty0 - 1 + fy) < Hn) & ((unsigned)(tx0 - 1 + fx + 1) < Wn);

            // hoisted input window: 3 ch x 3 rows x 4 cols, 8B-aligned LDS.64 loads
            float r[3][3][4];
            #pragma unroll
            for (int c = 0; c < 3; c++)
                #pragma unroll
                for (int ky = 0; ky < 3; ky++) {
                    const float* rp = &s_in[c*ID*ID + (fy + ky)*ID + fx];
                    const float2 q0 = *(const float2*)rp;
                    const float2 q1 = *(const float2*)(rp + 2);
                    r[c][ky][0] = q0.x; r[c][ky][1] = q0.y;
                    r[c][ky][2] = q1.x; r[c][ky][3] = q1.y;
                }

            const int po = fy*FDPH + fx;
            #pragma unroll
            for (int h = 0; h < 2; h++) {
                ull aA[4], aB[4];
                #pragma unroll
                for (int p = 0; p < 4; p++) { aA[p] = b1p[4*h + p]; aB[p] = b1p[4*h + p]; }

                #pragma unroll
                for (int j = 0; j < 27; j++) {
                    const int c  = j / 9;
                    const int r9 = j - c * 9;
                    const int ky = r9 / 3, kx = r9 - ky * 3;
                    const ull vA2 = pack2(r[c][ky][kx],     r[c][ky][kx]);
                    const ull vB2 = pack2(r[c][ky][kx + 1], r[c][ky][kx + 1]);
                    const ulonglong2* wp = (const ulonglong2*)&s_w1t[j*16 + h*8];
                    const ulonglong2 w01 = wp[0], w23 = wp[1];
                    ffma2(aA[0], vA2, w01.x); ffma2(aA[1], vA2, w01.y);
                    ffma2(aA[2], vA2, w23.x); ffma2(aA[3], vA2, w23.y);
                    ffma2(aB[0], vB2, w01.x); ffma2(aB[1], vB2, w01.y);
                    ffma2(aB[2], vB2, w23.x); ffma2(aB[3], vB2, w23.y);
                }

                #pragma unroll
                for (int p = 0; p < 4; p++) {
                    const int ch = 8*h + 2*p;
                    float g0A, g1A, g0B, g1B;
                    unpack2(gelu2(aA[p]), g0A, g1A);
                    unpack2(gelu2(aB[p]), g0B, g1B);
                    g0A = okA ? g0A : 0.f; g1A = okA ? g1A : 0.f;
                    g0B = okB ? g0B : 0.f; g1B = okB ? g1B : 0.f;
                    // adjacent pixels -> one half2 store per channel (4B aligned: fx even)
                    *(__half2*)&s_feat_h[ch    *FD*FDPH + po] = __floats2half2_rn(g0A, g0B);
                    *(__half2*)&s_feat_h[(ch+1)*FD*FDPH + po] = __floats2half2_rn(g1A, g1B);
                }
            }
        }
    }
    __syncthreads();

    // ---- phase 3: conv2 (active taps) + bilinear; f32x2 x-pairs, fp16 feat ----
    const int x0  = (tid & 7) * 4;
    const int row = tid >> 3;
    const float* img = pm25 + (size_t)b * Hn * Wn;
    float* s_wdup = s_in;    // dead region; [j][c]{wdy,wdy,wdx,wdx} = 576 floats

    float acc[4] = {0.f, 0.f, 0.f, 0.f};

    for (int k = 0; k < 9; k++) {
        const float wkv = s_wk[k];
        if (wkv == 0.0f) continue;          // uniform across block, value-exact
        const int kdy = k / 3 - 1, kdx = k - (k/3)*3 - 1;

        __syncthreads();
        for (int i = tid; i < 144; i += 256) {
            const int c = i / 9, j = i - c * 9;
            const float wy = __ldg(&w2[(size_t)(2*k)    *144 + c*9 + j]);
            const float wx = __ldg(&w2[(size_t)(2*k + 1)*144 + c*9 + j]);
            float* p = &s_wdup[(j*16 + c)*4];
            p[0] = wy; p[1] = wy; p[2] = wx; p[3] = wx;
        }
        __syncthreads();

        const float bdy = s_b2[2*k], bdx = s_b2[2*k + 1];
        ull ady0 = pack2(bdy, bdy), ady1 = ady0;
        ull adx0 = pack2(bdx, bdx), adx1 = adx0;

        #pragma unroll
        for (int c = 0; c < 16; c++) {
            const __half* fb = s_feat_h + c*FD*FDPH + row*FDPH + x0;
            #pragma unroll
            for (int ky = 0; ky < 3; ky++) {
                const __half* rp = fb + ky*FDPH;
                const uint2 q = *(const uint2*)(rp);              // 8B: h0..h3
                const __half2 h01 = *(const __half2*)&q.x;
                const __half2 h23 = *(const __half2*)&q.y;
                const __half2 h45 = *(const __half2*)(rp + 4);    // 4B: h4,h5
                const float2 e0 = __half22float2(h01);
                const float2 e1 = __half22float2(h23);
                const float2 e2 = __half22float2(h45);
                const ull P0 = pack2(e0.x, e0.y);
                const ull P1 = pack2(e0.y, e1.x);
                const ull P2 = pack2(e1.x, e1.y);
                const ull P3 = pack2(e1.y, e2.x);
                const ull P4 = pack2(e2.x, e2.y);

                const ulonglong2 wv0 = *(const ulonglong2*)&s_wdup[((ky*3+0)*16 + c)*4];
                const ulonglong2 wv1 = *(const ulonglong2*)&s_wdup[((ky*3+1)*16 + c)*4];
                const ulonglong2 wv2 = *(const ulonglong2*)&s_wdup[((ky*3+2)*16 + c)*4];
                ffma2(ady0, P0, wv0.x); ffma2(ady1, P2, wv0.x);
                ffma2(adx0, P0, wv0.y); ffma2(adx1, P2, wv0.y);
                ffma2(ady0, P1, wv1.x); ffma2(ady1, P3, wv1.x);
                ffma2(adx0, P1, wv1.y); ffma2(adx1, P3, wv1.y);
                ffma2(ady0, P2, wv2.x); ffma2(ady1, P4, wv2.x);
                ffma2(adx0, P2, wv2.y); ffma2(adx1, P4, wv2.y);
            }
        }

        float dyv[4], dxv[4];
        unpack2(ady0, dyv[0], dyv[1]); unpack2(ady1, dyv[2], dyv[3]);
        unpack2(adx0, dxv[0], dxv[1]); unpack2(adx1, dxv[2], dxv[3]);

        #pragma unroll
        for (int i = 0; i < 4; i++) {
            const int gy = ty0 + row;
            const int gx = tx0 + x0 + i;
            const float py = (float)(gy + kdy) + dyv[i];
            const float px = (float)(gx + kdx) + dxv[i];
            const float y0f = floorf(py), x0f = floorf(px);
            const float wy = py - y0f, wx = px - x0f;
            const int yy0 = (int)y0f, xx0 = (int)x0f;
            const int yy1 = yy0 + 1,  xx1 = xx0 + 1;
            const bool okY0 = (yy0 >= 0) & (yy0 < Hn);
            const bool okY1 = (yy1 >= 0) & (yy1 < Hn);
            const bool okX0 = (xx0 >= 0) & (xx0 < Wn);
            const bool okX1 = (xx1 >= 0) & (xx1 < Wn);
            const float v00 = (okY0 & okX0) ? __ldg(img + (size_t)yy0*Wn + xx0) : 0.f;
            const float v01 = (okY0 & okX1) ? __ldg(img + (size_t)yy0*Wn + xx1) : 0.f;
            const float v10 = (okY1 & okX0) ? __ldg(img + (size_t)yy1*Wn + xx0) : 0.f;
            const float v11 = (okY1 & okX1) ? __ldg(img + (size_t)yy1*Wn + xx1) : 0.f;
            const float s = v00*(1.f - wy)*(1.f - wx) + v01*(1.f - wy)*wx
                          + v10*wy*(1.f - wx)         + v11*wy*wx;
            acc[i] = fmaf(wkv, s, acc[i]);
        }
    }

    float4 o4; o4.x = acc[0]; o4.y = acc[1]; o4.z = acc[2]; o4.w = acc[3];
    *(float4*)&out[(size_t)b * Hn * Wn + (size_t)(ty0 + row) * Wn + (tx0 + x0)] = o4;
}

extern "C" void kernel_launch(void* const* d_in, const int* in_sizes, int n_in,
                              void* d_out, int out_size)
{
    const float* pm25 = (const float*)d_in[0];
    const float* wind = (const float*)d_in[1];
    const float* topo = (const float*)d_in[2];
    const float* w1   = (const float*)d_in[3];
    const float* b1   = (const float*)d_in[4];
    const float* w2   = (const float*)d_in[5];
    const float* b2   = (const float*)d_in[6];
    const float* wk   = (const float*)d_in[7];
    float* out = (float*)d_out;

    const size_t smem_bytes = (size_t)SMEM_FLOATS * sizeof(float);
    cudaFuncSetAttribute(fused_residual_advection,
                         cudaFuncAttributeMaxDynamicSharedMemorySize,
                         (int)smem_bytes);

    dim3 grid(Wn / TILE, Hn / TILE, Bn);
    fused_residual_advection<<<grid, 256, smem_bytes>>>(
        pm25, wind, topo, w1, b1, w2, b2, wk, out);
}

// round 10
// speedup vs baseline: 1.7806x; 1.0601x over previous
#include <cuda_runtime.h>
#include <cuda_fp16.h>
#include <math.h>

// Fixed problem shape: B=16, H=W=512
#define Bn 16
#define Hn 512
#define Wn 512
#define TILE 32
#define FD  34       // feat rows/cols (halo 1)
#define FDPH 40      // feat pitch in halves (80B rows, 8B-aligned accesses)
#define ID  36       // input tile with halo 2

// smem floats: s_in 3888 | feat(fp16) 10880 | w1t 432 | b1 16 | b2 18 | wk 9
#define SMEM_FLOATS (3*ID*ID + (16*FD*FDPH)/2 + 432 + 16 + 18 + 9)

typedef unsigned long long ull;

__device__ __forceinline__ ull pack2(float lo, float hi) {
    ull r; asm("mov.b64 %0, {%1, %2};" : "=l"(r) : "f"(lo), "f"(hi)); return r;
}
__device__ __forceinline__ void unpack2(ull v, float& lo, float& hi) {
    asm("mov.b64 {%0, %1}, %2;" : "=f"(lo), "=f"(hi) : "l"(v));
}
__device__ __forceinline__ void ffma2(ull& d, ull a, ull b) {
    asm("fma.rn.f32x2 %0, %1, %2, %0;" : "+l"(d) : "l"(a), "l"(b));
}
__device__ __forceinline__ ull fma2v(ull a, ull b, ull c) {
    ull r; asm("fma.rn.f32x2 %0, %1, %2, %3;" : "=l"(r) : "l"(a), "l"(b), "l"(c)); return r;
}
__device__ __forceinline__ ull mul2(ull a, ull b) {
    ull r; asm("mul.rn.f32x2 %0, %1, %2;" : "=l"(r) : "l"(a), "l"(b)); return r;
}

// GELU on 2 packed fp32 lanes via tanh-form approximation:
// gelu(x) = x * sigmoid(1.59577x + 0.0713548x^3)   (= tanh approx, since
// 0.5(1+tanh z) = sigmoid(2z)).  |gelu err| ~ 3e-4 abs — well inside the
// error budget (fp16 feat rounding already dominates at 5e-4).
__device__ __forceinline__ ull gelu2(ull x2) {
    ull xsq = mul2(x2, x2);
    ull t = fma2v(xsq, pack2(0.07135481627f, 0.07135481627f),
                        pack2(1.59576912161f, 1.59576912161f));
    ull y = mul2(x2, t);
    ull z = mul2(y, pack2(-1.44269504089f, -1.44269504089f));  // -y*log2(e)
    float zlo, zhi; unpack2(z, zlo, zhi);
    float elo, ehi;
    asm("ex2.approx.f32 %0, %1;" : "=f"(elo) : "f"(zlo));
    asm("ex2.approx.f32 %0, %1;" : "=f"(ehi) : "f"(zhi));
    float dlo = 1.0f + elo, dhi = 1.0f + ehi;
    float slo, shi;
    asm("rcp.approx.f32 %0, %1;" : "=f"(slo) : "f"(dlo));
    asm("rcp.approx.f32 %0, %1;" : "=f"(shi) : "f"(dhi));
    return mul2(x2, pack2(slo, shi));
}

__global__ __launch_bounds__(256, 3)
void fused_residual_advection(const float* __restrict__ pm25,
                              const float* __restrict__ wind,
                              const float* __restrict__ topo,
                              const float* __restrict__ w1,
                              const float* __restrict__ b1,
                              const float* __restrict__ w2,
                              const float* __restrict__ b2,
                              const float* __restrict__ wk,
                              float* __restrict__ out)
{
    extern __shared__ float smem[];
    float*  s_in     = smem;                             // [3][36][36]; phase3: dup-w table
    __half* s_feat_h = (__half*)(s_in + 3*ID*ID);        // [16][34][40] halves
    float*  s_w1t    = s_in + 3*ID*ID + (16*FD*FDPH)/2;  // [27][16]
    float*  s_b1     = s_w1t + 432;
    float*  s_b2     = s_b1 + 16;
    float*  s_wk     = s_b2 + 18;

    const int tid = threadIdx.x;
    const int b   = blockIdx.z;
    const int ty0 = blockIdx.y * TILE;
    const int tx0 = blockIdx.x * TILE;

    for (int i = tid; i < 432; i += 256) {
        int o = i / 27, j = i - o * 27;
        s_w1t[j*16 + o] = w1[i];
    }
    if (tid < 16) s_b1[tid] = b1[tid];
    else if (tid >= 32 && tid < 50) s_b2[tid - 32] = b2[tid - 32];
    else if (tid >= 64 && tid < 73) s_wk[tid - 64] = wk[tid - 64];

    const int gy0 = ty0 - 2, gx0 = tx0 - 2;
    const float* wind0 = wind + (size_t)b * 2 * Hn * Wn;
    const float* wind1 = wind0 + Hn * Wn;
    const float* topob = topo + (size_t)b * Hn * Wn;
    for (int i = tid; i < ID*ID; i += 256) {
        int ly = i / ID, lx = i - ly * ID;
        int gy = gy0 + ly, gx = gx0 + lx;
        bool ok = (gy >= 0) & (gy < Hn) & (gx >= 0) & (gx < Wn);
        size_t gidx = (size_t)gy * Wn + gx;
        s_in[0*ID*ID + i] = ok ? __ldg(wind0 + gidx) : 0.f;
        s_in[1*ID*ID + i] = ok ? __ldg(wind1 + gidx) : 0.f;
        s_in[2*ID*ID + i] = ok ? __ldg(topob + gidx) : 0.f;
    }
    __syncthreads();

    // ---- phase 2: conv1 + GELU -> fp16 feat ----
    // Adjacent pixel pairs (fx even, fx+1): shared 3x4x3 input window hoisted to
    // 36 regs (18 LDS.64), reused across both channel-halves; half2 feat stores.
    {
        ull b1p[8];
        #pragma unroll
        for (int p = 0; p < 8; p++) b1p[p] = pack2(s_b1[2*p], s_b1[2*p + 1]);

        const int npairs = (FD*FD)/2;   // 578; pair p -> linear pixels 2p, 2p+1
        for (int pi = tid; pi < npairs; pi += 256) {
            const int lin = 2*pi;
            const int fy = lin / FD, fx = lin - fy * FD;   // fx even, fx+1 <= 33
            const bool okA = ((unsigned)(ty0 - 1 + fy) < Hn) & ((unsigned)(tx0 - 1 + fx)     < Wn);
            const bool okB = ((unsigned)(ty0 - 1 + fy) < Hn) & ((unsigned)(tx0 - 1 + fx + 1) < Wn);

            // hoisted input window: 3 ch x 3 rows x 4 cols, 8B-aligned LDS.64 loads
            float r[3][3][4];
            #pragma unroll
            for (int c = 0; c < 3; c++)
                #pragma unroll
                for (int ky = 0; ky < 3; ky++) {
                    const float* rp = &s_in[c*ID*ID + (fy + ky)*ID + fx];
                    const float2 q0 = *(const float2*)rp;
                    const float2 q1 = *(const float2*)(rp + 2);
                    r[c][ky][0] = q0.x; r[c][ky][1] = q0.y;
                    r[c][ky][2] = q1.x; r[c][ky][3] = q1.y;
                }

            const int po = fy*FDPH + fx;
            #pragma unroll
            for (int h = 0; h < 2; h++) {
                ull aA[4], aB[4];
                #pragma unroll
                for (int p = 0; p < 4; p++) { aA[p] = b1p[4*h + p]; aB[p] = b1p[4*h + p]; }

                #pragma unroll
                for (int j = 0; j < 27; j++) {
                    const int c  = j / 9;
                    const int r9 = j - c * 9;
                    const int ky = r9 / 3, kx = r9 - ky * 3;
                    const ull vA2 = pack2(r[c][ky][kx],     r[c][ky][kx]);
                    const ull vB2 = pack2(r[c][ky][kx + 1], r[c][ky][kx + 1]);
                    const ulonglong2* wp = (const ulonglong2*)&s_w1t[j*16 + h*8];
                    const ulonglong2 w01 = wp[0], w23 = wp[1];
                    ffma2(aA[0], vA2, w01.x); ffma2(aA[1], vA2, w01.y);
                    ffma2(aA[2], vA2, w23.x); ffma2(aA[3], vA2, w23.y);
                    ffma2(aB[0], vB2, w01.x); ffma2(aB[1], vB2, w01.y);
                    ffma2(aB[2], vB2, w23.x); ffma2(aB[3], vB2, w23.y);
                }

                #pragma unroll
                for (int p = 0; p < 4; p++) {
                    const int ch = 8*h + 2*p;
                    float g0A, g1A, g0B, g1B;
                    unpack2(gelu2(aA[p]), g0A, g1A);
                    unpack2(gelu2(aB[p]), g0B, g1B);
                    g0A = okA ? g0A : 0.f; g1A = okA ? g1A : 0.f;
                    g0B = okB ? g0B : 0.f; g1B = okB ? g1B : 0.f;
                    *(__half2*)&s_feat_h[ch    *FD*FDPH + po] = __floats2half2_rn(g0A, g0B);
                    *(__half2*)&s_feat_h[(ch+1)*FD*FDPH + po] = __floats2half2_rn(g1A, g1B);
                }
            }
        }
    }
    __syncthreads();

    // ---- phase 3: conv2 (active taps) + bilinear; f32x2 x-pairs, fp16 feat ----
    const int x0  = (tid & 7) * 4;
    const int row = tid >> 3;
    const float* img = pm25 + (size_t)b * Hn * Wn;
    float* s_wdup = s_in;    // dead region; [j][c]{wdy,wdy,wdx,wdx} = 576 floats

    float acc[4] = {0.f, 0.f, 0.f, 0.f};

    for (int k = 0; k < 9; k++) {
        const float wkv = s_wk[k];
        if (wkv == 0.0f) continue;          // uniform across block, value-exact
        const int kdy = k / 3 - 1, kdx = k - (k/3)*3 - 1;

        __syncthreads();
        for (int i = tid; i < 144; i += 256) {
            const int c = i / 9, j = i - c * 9;
            const float wy = __ldg(&w2[(size_t)(2*k)    *144 + c*9 + j]);
            const float wx = __ldg(&w2[(size_t)(2*k + 1)*144 + c*9 + j]);
            float* p = &s_wdup[(j*16 + c)*4];
            p[0] = wy; p[1] = wy; p[2] = wx; p[3] = wx;
        }
        __syncthreads();

        const float bdy = s_b2[2*k], bdx = s_b2[2*k + 1];
        ull ady0 = pack2(bdy, bdy), ady1 = ady0;
        ull adx0 = pack2(bdx, bdx), adx1 = adx0;

        #pragma unroll
        for (int c = 0; c < 16; c++) {
            const __half* fb = s_feat_h + c*FD*FDPH + row*FDPH + x0;
            #pragma unroll
            for (int ky = 0; ky < 3; ky++) {
                const __half* rp = fb + ky*FDPH;
                const uint2 q = *(const uint2*)(rp);              // 8B: h0..h3
                const __half2 h01 = *(const __half2*)&q.x;
                const __half2 h23 = *(const __half2*)&q.y;
                const __half2 h45 = *(const __half2*)(rp + 4);    // 4B: h4,h5
                const float2 e0 = __half22float2(h01);
                const float2 e1 = __half22float2(h23);
                const float2 e2 = __half22float2(h45);
                const ull P0 = pack2(e0.x, e0.y);
                const ull P1 = pack2(e0.y, e1.x);
                const ull P2 = pack2(e1.x, e1.y);
                const ull P3 = pack2(e1.y, e2.x);
                const ull P4 = pack2(e2.x, e2.y);

                const ulonglong2 wv0 = *(const ulonglong2*)&s_wdup[((ky*3+0)*16 + c)*4];
                const ulonglong2 wv1 = *(const ulonglong2*)&s_wdup[((ky*3+1)*16 + c)*4];
                const ulonglong2 wv2 = *(const ulonglong2*)&s_wdup[((ky*3+2)*16 + c)*4];
                ffma2(ady0, P0, wv0.x); ffma2(ady1, P2, wv0.x);
                ffma2(adx0, P0, wv0.y); ffma2(adx1, P2, wv0.y);
                ffma2(ady0, P1, wv1.x); ffma2(ady1, P3, wv1.x);
                ffma2(adx0, P1, wv1.y); ffma2(adx1, P3, wv1.y);
                ffma2(ady0, P2, wv2.x); ffma2(ady1, P4, wv2.x);
                ffma2(adx0, P2, wv2.y); ffma2(adx1, P4, wv2.y);
            }
        }

        float dyv[4], dxv[4];
        unpack2(ady0, dyv[0], dyv[1]); unpack2(ady1, dyv[2], dyv[3]);
        unpack2(adx0, dxv[0], dxv[1]); unpack2(adx1, dxv[2], dxv[3]);

        #pragma unroll
        for (int i = 0; i < 4; i++) {
            const int gy = ty0 + row;
            const int gx = tx0 + x0 + i;
            const float py = (float)(gy + kdy) + dyv[i];
            const float px = (float)(gx + kdx) + dxv[i];
            const float y0f = floorf(py), x0f = floorf(px);
            const float wy = py - y0f, wx = px - x0f;
            const int yy0 = (int)y0f, xx0 = (int)x0f;
            const int yy1 = yy0 + 1,  xx1 = xx0 + 1;
            const bool okY0 = (yy0 >= 0) & (yy0 < Hn);
            const bool okY1 = (yy1 >= 0) & (yy1 < Hn);
            const bool okX0 = (xx0 >= 0) & (xx0 < Wn);
            const bool okX1 = (xx1 >= 0) & (xx1 < Wn);
            const float v00 = (okY0 & okX0) ? __ldg(img + (size_t)yy0*Wn + xx0) : 0.f;
            const float v01 = (okY0 & okX1) ? __ldg(img + (size_t)yy0*Wn + xx1) : 0.f;
            const float v10 = (okY1 & okX0) ? __ldg(img + (size_t)yy1*Wn + xx0) : 0.f;
            const float v11 = (okY1 & okX1) ? __ldg(img + (size_t)yy1*Wn + xx1) : 0.f;
            const float s = v00*(1.f - wy)*(1.f - wx) + v01*(1.f - wy)*wx
                          + v10*wy*(1.f - wx)         + v11*wy*wx;
            acc[i] = fmaf(wkv, s, acc[i]);
        }
    }

    float4 o4; o4.x = acc[0]; o4.y = acc[1]; o4.z = acc[2]; o4.w = acc[3];
    *(float4*)&out[(size_t)b * Hn * Wn + (size_t)(ty0 + row) * Wn + (tx0 + x0)] = o4;
}

extern "C" void kernel_launch(void* const* d_in, const int* in_sizes, int n_in,
                              void* d_out, int out_size)
{
    const float* pm25 = (const float*)d_in[0];
    const float* wind = (const float*)d_in[1];
    const float* topo = (const float*)d_in[2];
    const float* w1   = (const float*)d_in[3];
    const float* b1   = (const float*)d_in[4];
    const float* w2   = (const float*)d_in[5];
    const float* b2   = (const float*)d_in[6];
    const float* wk   = (const float*)d_in[7];
    float* out = (float*)d_out;

    const size_t smem_bytes = (size_t)SMEM_FLOATS * sizeof(float);
    cudaFuncSetAttribute(fused_residual_advection,
                         cudaFuncAttributeMaxDynamicSharedMemorySize,
                         (int)smem_bytes);

    dim3 grid(Wn / TILE, Hn / TILE, Bn);
    fused_residual_advection<<<grid, 256, smem_bytes>>>(
        pm25, wind, topo, w1, b1, w2, b2, wk, out);
}